// round 3
// baseline (speedup 1.0000x reference)
#include <cuda_runtime.h>
#include <cuda_bf16.h>
#include <cstdint>

// ---------------- problem constants ----------------
constexpr int T    = 48;     // Tm1
constexpr int M    = 128;    // m == p
constexpr int R    = 4;      // rows per CTA
constexpr int NT   = 256;    // threads per CTA
constexpr int NCTA = 8192 / R;

// ---------------- device scratch: transposed weights ----------------
__device__ float g_WdT[128 * 128];   // [k][j] = W1[j][k]
__device__ float g_WcT[128 * 128];   // [k][j] = W1[j][128+k]
__device__ float g_WxT[128 * 128];   // [k][j] = W1[j][256+k]
__device__ float g_WhhT[128 * 512];  // [k][jj] = Whh[jj][k]

// ---------------- helpers ----------------
__device__ __forceinline__ float warp_sum(float v) {
#pragma unroll
    for (int o = 16; o; o >>= 1) v += __shfl_xor_sync(0xffffffffu, v, o);
    return v;
}
__device__ __forceinline__ float warp_max(float v) {
#pragma unroll
    for (int o = 16; o; o >>= 1) v = fmaxf(v, __shfl_xor_sync(0xffffffffu, v, o));
    return v;
}
__device__ __forceinline__ float tanh_fast(float x) {  // MUFU.TANH, 1 op
    float y;
    asm("tanh.approx.f32 %0, %1;" : "=f"(y) : "f"(x));
    return y;
}
__device__ __forceinline__ float tanh_acc(float x) {   // accurate (~1e-7)
    float e = __expf(2.0f * x);
    return 1.0f - __fdividef(2.0f, e + 1.0f);
}
__device__ __forceinline__ float sigm(float x) {
    return __fdividef(1.0f, 1.0f + __expf(-x));
}
#define F4C(v, kk) ((kk) == 0 ? (v).x : (kk) == 1 ? (v).y : (kk) == 2 ? (v).z : (v).w)

// ---------------- prep: weight transposes ----------------
__global__ void prep_kernel(const float* __restrict__ W1, const float* __restrict__ Whh) {
    int idx = blockIdx.x * blockDim.x + threadIdx.x;
    if (idx < 65536) {
        int k = idx >> 9, jj = idx & 511;
        g_WhhT[idx] = Whh[jj * 128 + k];
    }
    if (idx < 16384) {
        int k = idx >> 7, j = idx & 127;
        g_WdT[idx] = W1[j * 384 + k];
        g_WcT[idx] = W1[j * 384 + 128 + k];
        g_WxT[idx] = W1[j * 384 + 256 + k];
    }
}

// ---------------- GRU + linear side branch: out[b] = s_skip + s_linear ----------------
__global__ __launch_bounds__(128) void gru_kernel(
    const float* __restrict__ y_skip, const float* __restrict__ y_prev,
    const float* __restrict__ gWih, const float* __restrict__ gWhh,
    const float* __restrict__ gbih, const float* __restrict__ gbhh,
    const float* __restrict__ l1W, const float* __restrict__ l1b,
    const float* __restrict__ l2W, const float* __restrict__ l2b,
    float* __restrict__ out)
{
    __shared__ float s[200];
    int tid = threadIdx.x;
    for (int i = tid; i < 15; i += 128) { s[i] = gWih[i]; s[96 + i] = gbih[i]; s[112 + i] = gbhh[i]; }
    for (int i = tid; i < 75; i += 128) s[16 + i] = gWhh[i];
    for (int i = tid; i < 5;  i += 128) s[128 + i] = l1W[i];
    for (int i = tid; i < 48; i += 128) s[144 + i] = l2W[i];
    if (tid == 0) { s[192] = l1b[0]; s[193] = l2b[0]; }
    __syncthreads();

    int b = blockIdx.x * 128 + tid;
    float h[5] = {0.f, 0.f, 0.f, 0.f, 0.f};
#pragma unroll 1
    for (int t = 0; t < 24; t++) {
        float x = y_skip[b * 24 + t];
        float gh[15];
#pragma unroll
        for (int jj = 0; jj < 15; jj++) {
            float a = s[112 + jj];
#pragma unroll
            for (int k = 0; k < 5; k++) a += s[16 + jj * 5 + k] * h[k];
            gh[jj] = a;
        }
#pragma unroll
        for (int q = 0; q < 5; q++) {
            float rr = sigm(s[q] * x + s[96 + q] + gh[q]);
            float zz = sigm(s[5 + q] * x + s[101 + q] + gh[5 + q]);
            float nn = tanh_acc(s[10 + q] * x + s[106 + q] + rr * gh[10 + q]);
            h[q] = (1.0f - zz) * nn + zz * h[q];
        }
    }
    float acc = s[192];
#pragma unroll
    for (int q = 0; q < 5; q++) acc += h[q] * s[128 + q];
    float s2 = s[193];
#pragma unroll 8
    for (int t = 0; t < 48; t++) s2 += y_prev[(size_t)b * 48 + t] * s[144 + t];
    out[b] = acc + s2;
}

// ---------------- SMEM layout (float offsets) ----------------
constexpr int XW_S  = 129;                    // padded stride for XW
constexpr int O_XS  = 0;                      // [R*T*128]      = 24576
constexpr int O_XW  = O_XS + R * T * 128;     // [R*T*129]      = 24768
constexpr int O_DS  = O_XW + R * T * XW_S;    // ds [R*128]
constexpr int O_CS  = O_DS + R * 128;         // cs [R*128]
constexpr int O_DP  = O_CS + R * 128;         // dpart [R*128]
constexpr int O_CT  = O_DP + R * 128;         // context [R*128]
constexpr int O_GS  = O_CT + R * 128;         // gates / scratch [R*512]
constexpr int O_EB  = O_GS + R * 512;         // e / beta [R*48]
constexpr int O_YP  = O_EB + R * T;           // staged y_prev [R*48]
constexpr int O_YT  = O_YP + R * T;           // y_tilde [8]
constexpr int O_W2  = O_YT + 8;               // [128]
constexpr int O_B1  = O_W2 + 128;             // [128]
constexpr int O_WIH = O_B1 + 128;             // [512]
constexpr int O_BIA = O_WIH + 512;            // [512] bih+bhh
constexpr int O_FCW = O_BIA + 512;            // [130] fc_W + fc_b
constexpr int O_FCF = O_FCW + 130;            // [257] fcf_W + fcf_b
constexpr int SM_FLOATS  = O_FCF + 257;
constexpr int SMEM_BYTES = SM_FLOATS * 4;     // ~222 KB

// ---------------- main persistent decoder ----------------
__global__ __launch_bounds__(NT, 1) void decoder_kernel(
    const float* __restrict__ X, const float* __restrict__ yprev,
    const float* __restrict__ ab1, const float* __restrict__ aW2,
    const float* __restrict__ lWih, const float* __restrict__ lbih, const float* __restrict__ lbhh,
    const float* __restrict__ fcW, const float* __restrict__ fcb,
    const float* __restrict__ fcfW, const float* __restrict__ fcfb,
    float* __restrict__ out)
{
    extern __shared__ float sm[];
    const int tid = threadIdx.x;
    const int b0  = blockIdx.x * R;

    // ---- stage X (float4), smalls, y_prev; zero ds/cs ----
    {
        const float4* src = reinterpret_cast<const float4*>(X + (size_t)b0 * T * 128);
        float4* dst = reinterpret_cast<float4*>(sm + O_XS);
        for (int i = tid; i < R * T * 128 / 4; i += NT) dst[i] = src[i];
    }
    for (int i = tid; i < 128; i += NT) { sm[O_W2 + i] = aW2[i]; sm[O_B1 + i] = ab1[i]; }
    for (int i = tid; i < 512; i += NT) { sm[O_WIH + i] = lWih[i]; sm[O_BIA + i] = lbih[i] + lbhh[i]; }
    for (int i = tid; i < 129; i += NT) sm[O_FCW + i] = fcW[i];
    for (int i = tid; i < 256; i += NT) sm[O_FCF + i] = fcfW[i];
    if (tid == 0) { sm[O_FCW + 129] = fcb[0]; sm[O_FCF + 256] = fcfb[0]; }
    for (int i = tid; i < R * T; i += NT) {
        int r = i / T, tt = i % T;
        sm[O_YP + i] = yprev[(size_t)(b0 + r) * T + tt];
    }
    for (int i = tid; i < 2 * R * 128; i += NT) sm[O_DS + i] = 0.0f;  // ds+cs contiguous
    __syncthreads();

    // ---- phase 0: XW[p][j] = sum_k X[p][k] * Wx[k][j]   (p = r*48+tt) ----
    {
        const int j = tid & 127, g = tid >> 7;
#pragma unroll 1
        for (int pb = 0; pb < 12; ++pb) {
            const int pbase = g * 96 + pb * 8;
            float acc[8] = {0, 0, 0, 0, 0, 0, 0, 0};
#pragma unroll 2
            for (int k4 = 0; k4 < 32; ++k4) {
                float4 xv[8];
#pragma unroll
                for (int q = 0; q < 8; ++q)
                    xv[q] = *reinterpret_cast<const float4*>(&sm[O_XS + (pbase + q) * 128 + k4 * 4]);
#pragma unroll
                for (int kk = 0; kk < 4; ++kk) {
                    float w = g_WxT[(k4 * 4 + kk) * 128 + j];
#pragma unroll
                    for (int q = 0; q < 8; ++q) acc[q] += F4C(xv[q], kk) * w;
                }
            }
#pragma unroll
            for (int q = 0; q < 8; ++q) sm[O_XW + (pbase + q) * XW_S + j] = acc[q];
        }
    }
    __syncthreads();

    // ---- main recurrence ----
#pragma unroll 1
    for (int t = 0; t < T; ++t) {
        // A1: dpart partials (k-split halves so Wd/Wc read exactly once)
        {
            const int j = tid & 127, g = tid >> 7, kb = g * 16;
            float acc[4] = {0, 0, 0, 0};
#pragma unroll 2
            for (int k4 = kb; k4 < kb + 16; ++k4) {
                float4 dv[4], cv[4];
#pragma unroll
                for (int r = 0; r < 4; ++r) {
                    dv[r] = *reinterpret_cast<const float4*>(&sm[O_DS + r * 128 + k4 * 4]);
                    cv[r] = *reinterpret_cast<const float4*>(&sm[O_CS + r * 128 + k4 * 4]);
                }
#pragma unroll
                for (int kk = 0; kk < 4; ++kk) {
                    float wd = g_WdT[(k4 * 4 + kk) * 128 + j];
                    float wc = g_WcT[(k4 * 4 + kk) * 128 + j];
#pragma unroll
                    for (int r = 0; r < 4; ++r)
                        acc[r] += wd * F4C(dv[r], kk) + wc * F4C(cv[r], kk);
                }
            }
#pragma unroll
            for (int r = 0; r < 4; ++r) sm[O_GS + g * 512 + r * 128 + j] = acc[r];
        }
        __syncthreads();
        // A2: combine halves + b1
        {
            int o = tid;            // covers 512 outputs in 2 chunks
            sm[O_DP + o] = sm[O_B1 + (o & 127)] + sm[O_GS + o] + sm[O_GS + 512 + o];
            o = tid + 256;
            // second chunk maps r=2,3 halves: GS layout is [g][r][j]
            sm[O_DP + o] = sm[O_B1 + (o & 127)] + sm[O_GS + o] + sm[O_GS + 512 + o];
        }
        __syncthreads();
        // B: e[p] = sum_j W2[j] * tanh(dpart[r][j] + XW[p][j])
        if (tid < R * T) {
            const int p = tid, r = p / T;
            const float* dp = &sm[O_DP + r * 128];
            const float* xw = &sm[O_XW + p * XW_S];
            float acc = 0.f;
#pragma unroll 8
            for (int j = 0; j < 128; ++j)
                acc += sm[O_W2 + j] * tanh_fast(dp[j] + xw[j]);
            sm[O_EB + p] = acc;
        }
        __syncthreads();
        // B2: softmax over tt per row (warp per row)
        if (tid < 128) {
            const int w = tid >> 5, l = tid & 31;
            float e0 = sm[O_EB + w * T + l];
            float e1 = (l < 16) ? sm[O_EB + w * T + 32 + l] : -3.4e38f;
            float mx = warp_max(fmaxf(e0, e1));
            float x0 = __expf(e0 - mx);
            float x1 = (l < 16) ? __expf(e1 - mx) : 0.f;
            float s  = warp_sum(x0 + x1);
            float inv = __fdividef(1.0f, s);
            sm[O_EB + w * T + l] = x0 * inv;
            if (l < 16) sm[O_EB + w * T + 32 + l] = x1 * inv;
        }
        __syncthreads();
        // C: context[r][k] = sum_tt beta[r][tt] * X[r][tt][k]
        {
            const int k = tid & 127, rA = tid >> 7, rB = rA + 2;
            float aA = 0.f, aB = 0.f;
#pragma unroll 4
            for (int tt = 0; tt < T; ++tt) {
                aA += sm[O_EB + rA * T + tt] * sm[O_XS + (rA * T + tt) * 128 + k];
                aB += sm[O_EB + rB * T + tt] * sm[O_XS + (rB * T + tt) * 128 + k];
            }
            sm[O_CT + rA * 128 + k] = aA;
            sm[O_CT + rB * 128 + k] = aB;
        }
        __syncthreads();
        // C2: y_tilde per row (warp per row)
        if (tid < 128) {
            const int w = tid >> 5, l = tid & 31;
            float a = 0.f;
#pragma unroll
            for (int q = 0; q < 4; ++q) {
                int k = l + 32 * q;
                a += sm[O_FCW + k] * sm[O_CT + w * 128 + k];
            }
            a = warp_sum(a);
            if (l == 0)
                sm[O_YT + w] = a + sm[O_FCW + 128] * sm[O_YP + w * T + t] + sm[O_FCW + 129];
        }
        __syncthreads();
        // D: gates[r][jj] = Whh-row dot d[r] + Wih[jj]*yt[r] + bias[jj]
        {
            const int jjA = tid, jjB = tid + 256;
            float yt[4];
#pragma unroll
            for (int r = 0; r < 4; ++r) yt[r] = sm[O_YT + r];
            float accA[4] = {0, 0, 0, 0}, accB[4] = {0, 0, 0, 0};
#pragma unroll 2
            for (int k4 = 0; k4 < 32; ++k4) {
                float4 dv[4];
#pragma unroll
                for (int r = 0; r < 4; ++r)
                    dv[r] = *reinterpret_cast<const float4*>(&sm[O_DS + r * 128 + k4 * 4]);
#pragma unroll
                for (int kk = 0; kk < 4; ++kk) {
                    float wA = g_WhhT[(k4 * 4 + kk) * 512 + jjA];
                    float wB = g_WhhT[(k4 * 4 + kk) * 512 + jjB];
#pragma unroll
                    for (int r = 0; r < 4; ++r) {
                        float d = F4C(dv[r], kk);
                        accA[r] += wA * d;
                        accB[r] += wB * d;
                    }
                }
            }
            float wihA = sm[O_WIH + jjA], wihB = sm[O_WIH + jjB];
            float biA = sm[O_BIA + jjA], biB = sm[O_BIA + jjB];
#pragma unroll
            for (int r = 0; r < 4; ++r) {
                sm[O_GS + r * 512 + jjA] = accA[r] + wihA * yt[r] + biA;
                sm[O_GS + r * 512 + jjB] = accB[r] + wihB * yt[r] + biB;
            }
        }
        __syncthreads();
        // E: LSTM pointwise update
        {
#pragma unroll
            for (int half = 0; half < 2; ++half) {
                const int o = tid + half * 256;
                const int r = o >> 7, q = o & 127;
                float gi = sm[O_GS + r * 512 + q];
                float gf = sm[O_GS + r * 512 + 128 + q];
                float gg = sm[O_GS + r * 512 + 256 + q];
                float go = sm[O_GS + r * 512 + 384 + q];
                float cn = sigm(gf) * sm[O_CS + r * 128 + q] + sigm(gi) * tanh_acc(gg);
                sm[O_CS + r * 128 + q] = cn;
                sm[O_DS + r * 128 + q] = sigm(go) * tanh_acc(cn);
            }
        }
        __syncthreads();
    }

    // ---- final: y_pred = fcf . [d, context] + fcf_b;  out += y_pred ----
    if (tid < 128) {
        const int w = tid >> 5, l = tid & 31;
        float a = 0.f;
#pragma unroll
        for (int q = 0; q < 4; ++q) {
            int k = l + 32 * q;
            a += sm[O_FCF + k] * sm[O_DS + w * 128 + k]
               + sm[O_FCF + 128 + k] * sm[O_CT + w * 128 + k];
        }
        a = warp_sum(a);
        if (l == 0) out[b0 + w] += a + sm[O_FCF + 256];
    }
}

// ---------------- launch ----------------
extern "C" void kernel_launch(void* const* d_in, const int* in_sizes, int n_in,
                              void* d_out, int out_size) {
    const float* X     = (const float*)d_in[0];
    const float* yprev = (const float*)d_in[1];
    const float* yskip = (const float*)d_in[2];
    const float* aW1   = (const float*)d_in[3];
    const float* ab1   = (const float*)d_in[4];
    const float* aW2   = (const float*)d_in[5];
    // d_in[6] = attn_b2 (softmax shift-invariant -> unused)
    const float* lWih  = (const float*)d_in[7];
    const float* lWhh  = (const float*)d_in[8];
    const float* lbih  = (const float*)d_in[9];
    const float* lbhh  = (const float*)d_in[10];
    const float* fcW   = (const float*)d_in[11];
    const float* fcb   = (const float*)d_in[12];
    const float* fcfW  = (const float*)d_in[13];
    const float* fcfb  = (const float*)d_in[14];
    const float* gWih  = (const float*)d_in[15];
    const float* gWhh  = (const float*)d_in[16];
    const float* gbih  = (const float*)d_in[17];
    const float* gbhh  = (const float*)d_in[18];
    const float* l1W   = (const float*)d_in[19];
    const float* l1b   = (const float*)d_in[20];
    const float* l2W   = (const float*)d_in[21];
    const float* l2b   = (const float*)d_in[22];
    float* out = (float*)d_out;

    cudaFuncSetAttribute(decoder_kernel, cudaFuncAttributeMaxDynamicSharedMemorySize, SMEM_BYTES);

    // side branch writes out[b] = s_skip + s_linear
    gru_kernel<<<8192 / 128, 128>>>(yskip, yprev, gWih, gWhh, gbih, gbhh,
                                    l1W, l1b, l2W, l2b, out);
    // weight transposes
    prep_kernel<<<256, 256>>>(aW1, lWhh);
    // main decoder adds y_pred into out
    decoder_kernel<<<NCTA, NT, SMEM_BYTES>>>(X, yprev, ab1, aW2,
                                             lWih, lbih, lbhh,
                                             fcW, fcb, fcfW, fcfb, out);
}

// round 4
// speedup vs baseline: 1.5764x; 1.5764x over previous
#include <cuda_runtime.h>
#include <cuda_fp16.h>
#include <cstdint>

// ---------------- problem constants ----------------
constexpr int T    = 48;     // Tm1
constexpr int R    = 8;      // rows per CTA
constexpr int NT   = 512;    // threads per CTA
constexpr int NCTA = 8192 / R;   // 1024

// ---------------- device scratch: k-paired transposed weights (fp32) ----------------
__device__ float2 g_WdT2[64 * 128];   // [k2][j] = (W1[j][2k2], W1[j][2k2+1])
__device__ float2 g_WcT2[64 * 128];   // offset +128
__device__ float2 g_WxT2[64 * 128];   // offset +256
__device__ float2 g_WhhT2[64 * 512];  // [k2][jj] = (Whh[jj][2k2], Whh[jj][2k2+1])

// ---------------- helpers ----------------
__device__ __forceinline__ void ffma2(float2& a, float2 x, float2 w) {
    asm("{\n\t"
        ".reg .b64 A, X, W;\n\t"
        "mov.b64 A, {%0, %1};\n\t"
        "mov.b64 X, {%2, %3};\n\t"
        "mov.b64 W, {%4, %5};\n\t"
        "fma.rn.f32x2 A, X, W, A;\n\t"
        "mov.b64 {%0, %1}, A;\n\t"
        "}"
        : "+f"(a.x), "+f"(a.y)
        : "f"(x.x), "f"(x.y), "f"(w.x), "f"(w.y));
}
__device__ __forceinline__ float warp_sum(float v) {
#pragma unroll
    for (int o = 16; o; o >>= 1) v += __shfl_xor_sync(0xffffffffu, v, o);
    return v;
}
__device__ __forceinline__ float warp_max(float v) {
#pragma unroll
    for (int o = 16; o; o >>= 1) v = fmaxf(v, __shfl_xor_sync(0xffffffffu, v, o));
    return v;
}
__device__ __forceinline__ float tanh_fast(float x) {  // MUFU.TANH
    float y;
    asm("tanh.approx.f32 %0, %1;" : "=f"(y) : "f"(x));
    return y;
}
__device__ __forceinline__ float tanh_acc(float x) {
    float e = __expf(2.0f * x);
    return 1.0f - __fdividef(2.0f, e + 1.0f);
}
__device__ __forceinline__ float sigm(float x) {
    return __fdividef(1.0f, 1.0f + __expf(-x));
}

// ---------------- prep: k-paired weight transposes ----------------
__global__ void prep_kernel(const float* __restrict__ W1, const float* __restrict__ Whh) {
    int idx = blockIdx.x * blockDim.x + threadIdx.x;
    if (idx < 32768) {  // Whh: 64 k2 x 512 jj
        int k2 = idx >> 9, jj = idx & 511;
        g_WhhT2[idx] = make_float2(Whh[jj * 128 + 2 * k2], Whh[jj * 128 + 2 * k2 + 1]);
    }
    if (idx < 8192) {   // 64 k2 x 128 j
        int k2 = idx >> 7, j = idx & 127;
        g_WdT2[idx] = make_float2(W1[j * 384 + 2 * k2],       W1[j * 384 + 2 * k2 + 1]);
        g_WcT2[idx] = make_float2(W1[j * 384 + 128 + 2 * k2], W1[j * 384 + 128 + 2 * k2 + 1]);
        g_WxT2[idx] = make_float2(W1[j * 384 + 256 + 2 * k2], W1[j * 384 + 256 + 2 * k2 + 1]);
    }
}

// ---------------- GRU + linear side branch: out[b] = s_skip + s_linear ----------------
__global__ __launch_bounds__(128) void gru_kernel(
    const float* __restrict__ y_skip, const float* __restrict__ y_prev,
    const float* __restrict__ gWih, const float* __restrict__ gWhh,
    const float* __restrict__ gbih, const float* __restrict__ gbhh,
    const float* __restrict__ l1W, const float* __restrict__ l1b,
    const float* __restrict__ l2W, const float* __restrict__ l2b,
    float* __restrict__ out)
{
    __shared__ float s[200];
    int tid = threadIdx.x;
    for (int i = tid; i < 15; i += 128) { s[i] = gWih[i]; s[96 + i] = gbih[i]; s[112 + i] = gbhh[i]; }
    for (int i = tid; i < 75; i += 128) s[16 + i] = gWhh[i];
    for (int i = tid; i < 5;  i += 128) s[128 + i] = l1W[i];
    for (int i = tid; i < 48; i += 128) s[144 + i] = l2W[i];
    if (tid == 0) { s[192] = l1b[0]; s[193] = l2b[0]; }
    __syncthreads();

    int b = blockIdx.x * 128 + tid;
    float h[5] = {0.f, 0.f, 0.f, 0.f, 0.f};
#pragma unroll 1
    for (int t = 0; t < 24; t++) {
        float x = y_skip[b * 24 + t];
        float gh[15];
#pragma unroll
        for (int jj = 0; jj < 15; jj++) {
            float a = s[112 + jj];
#pragma unroll
            for (int k = 0; k < 5; k++) a += s[16 + jj * 5 + k] * h[k];
            gh[jj] = a;
        }
#pragma unroll
        for (int q = 0; q < 5; q++) {
            float rr = sigm(s[q] * x + s[96 + q] + gh[q]);
            float zz = sigm(s[5 + q] * x + s[101 + q] + gh[5 + q]);
            float nn = tanh_acc(s[10 + q] * x + s[106 + q] + rr * gh[10 + q]);
            h[q] = (1.0f - zz) * nn + zz * h[q];
        }
    }
    float acc = s[192];
#pragma unroll
    for (int q = 0; q < 5; q++) acc += h[q] * s[128 + q];
    float s2 = s[193];
#pragma unroll 8
    for (int t = 0; t < 48; t++) s2 += y_prev[(size_t)b * 48 + t] * s[144 + t];
    out[b] = acc + s2;
}

// ---------------- SMEM layout (byte offsets) ----------------
constexpr int XW_S   = 130;                 // half stride (conflict-free: 130h=65 words, 65%32=1)
constexpr int OB_XS  = 0;                   // half [R*T*128]   98304B
constexpr int OB_XW  = 98304;               // half [R*T*130]   99840B
constexpr int OB_DS  = 198144;              // float [R*128]    4096B
constexpr int OB_CS  = 202240;              // float [R*128]    4096B
constexpr int OB_DP  = 206336;              // half  [R*128]    2048B
constexpr int OB_CT  = 208384;              // half  [R*128]    2048B
constexpr int OB_GS  = 210432;              // half  [4096]     8192B  (A1 partials / gates)
constexpr int OB_EB  = 218624;              // float [R*T]      1536B
constexpr int OB_YP  = 220160;              // float [R*T]      1536B
constexpr int OB_YT  = 221696;              // float [8]        32B
constexpr int OB_W2  = 221728;              // float [128]      512B
constexpr int OB_B1  = 222240;              // float [128]      512B
constexpr int OB_WIH = 222752;              // float [512]      2048B
constexpr int OB_BIA = 224800;              // float [512]      2048B
constexpr int OB_FCW = 226848;              // float [130]      520B
constexpr int OB_FCF = 227368;              // float [257]      1028B
constexpr int SMEM_BYTES = 228396;

// ---------------- main persistent decoder ----------------
__global__ __launch_bounds__(NT, 1) void decoder_kernel(
    const float* __restrict__ X, const float* __restrict__ yprev,
    const float* __restrict__ ab1, const float* __restrict__ aW2,
    const float* __restrict__ lWih, const float* __restrict__ lbih, const float* __restrict__ lbhh,
    const float* __restrict__ fcW, const float* __restrict__ fcb,
    const float* __restrict__ fcfW, const float* __restrict__ fcfb,
    float* __restrict__ out)
{
    extern __shared__ char smraw[];
    __half* XS = (__half*)(smraw + OB_XS);
    __half* XW = (__half*)(smraw + OB_XW);
    float*  DS = (float*)(smraw + OB_DS);
    float*  CS = (float*)(smraw + OB_CS);
    __half* DP = (__half*)(smraw + OB_DP);
    __half* CT = (__half*)(smraw + OB_CT);
    __half* GS = (__half*)(smraw + OB_GS);
    float*  EB = (float*)(smraw + OB_EB);
    float*  YP = (float*)(smraw + OB_YP);
    float*  YT = (float*)(smraw + OB_YT);
    float*  W2 = (float*)(smraw + OB_W2);
    float*  B1 = (float*)(smraw + OB_B1);
    float*  WIH = (float*)(smraw + OB_WIH);
    float*  BIA = (float*)(smraw + OB_BIA);
    float*  FCW = (float*)(smraw + OB_FCW);
    float*  FCF = (float*)(smraw + OB_FCF);
    float*  XTMP = DS;  // phase-0 staging reuses DS..GS region (20.5KB >= 16KB)

    const int tid = threadIdx.x;
    const int b0  = blockIdx.x * R;

    // ---- stage X (fp32 -> fp16), smalls, y_prev ----
    {
        const float2* src = reinterpret_cast<const float2*>(X + (size_t)b0 * T * 128);
        __half2* dst = reinterpret_cast<__half2*>(XS);
        for (int i = tid; i < R * T * 64; i += NT) {
            float2 v = src[i];
            dst[i] = __floats2half2_rn(v.x, v.y);
        }
    }
    for (int i = tid; i < 128; i += NT) { W2[i] = aW2[i]; B1[i] = ab1[i]; }
    for (int i = tid; i < 512; i += NT) { WIH[i] = lWih[i]; BIA[i] = lbih[i] + lbhh[i]; }
    for (int i = tid; i < 129; i += NT) FCW[i] = fcW[i];
    for (int i = tid; i < 256; i += NT) FCF[i] = fcfW[i];
    if (tid == 0) { FCW[129] = fcb[0]; FCF[256] = fcfb[0]; }
    for (int i = tid; i < R * T; i += NT) {
        int r = i / T, tt = i % T;
        YP[i] = yprev[(size_t)(b0 + r) * T + tt];
    }
    __syncthreads();

    // ---- phase 0: XW[p][j] = sum_k X[p][k] * Wx[k][j],  p = r*T+tt in [0,384) ----
    {
        const int j = tid & 127, g = tid >> 7;
#pragma unroll 1
        for (int pb = 0; pb < 12; ++pb) {
            // stage 32 rows (4 g-groups x 8) fp32 into XTMP
            for (int e = tid; e < 32 * 128; e += NT) {
                int row = e >> 7, col = e & 127;
                int p = (row >> 3) * 96 + pb * 8 + (row & 7);
                XTMP[e] = __half2float(XS[p * 128 + col]);
            }
            __syncthreads();
            float2 acc2[8];
#pragma unroll
            for (int q = 0; q < 8; ++q) acc2[q] = make_float2(0.f, 0.f);
#pragma unroll 4
            for (int k4 = 0; k4 < 32; ++k4) {
                float2 w0 = g_WxT2[(2 * k4) * 128 + j];
                float2 w1 = g_WxT2[(2 * k4 + 1) * 128 + j];
#pragma unroll
                for (int q = 0; q < 8; ++q) {
                    float4 xv = reinterpret_cast<const float4*>(XTMP + (g * 8 + q) * 128)[k4];
                    ffma2(acc2[q], make_float2(xv.x, xv.y), w0);
                    ffma2(acc2[q], make_float2(xv.z, xv.w), w1);
                }
            }
#pragma unroll
            for (int q = 0; q < 8; ++q) {
                int p = g * 96 + pb * 8 + q;
                XW[p * XW_S + j] = __float2half(acc2[q].x + acc2[q].y);
            }
            __syncthreads();
        }
    }
    // zero states (after phase0, which reused this region)
    for (int i = tid; i < 2 * R * 128; i += NT) DS[i] = 0.0f;  // DS+CS contiguous
    __syncthreads();

    // ---- main recurrence ----
#pragma unroll 1
    for (int t = 0; t < T; ++t) {
        // A1: dpart partials, 4-way k-split (g in [0,4)), j = tid&127
        {
            const int j = tid & 127, g = tid >> 7;
            float2 acc2[8];
#pragma unroll
            for (int r = 0; r < 8; ++r) acc2[r] = make_float2(0.f, 0.f);
            const int k4b = g * 8;
#pragma unroll 4
            for (int k4 = k4b; k4 < k4b + 8; ++k4) {
                float2 wd0 = g_WdT2[(2 * k4) * 128 + j];
                float2 wd1 = g_WdT2[(2 * k4 + 1) * 128 + j];
                float2 wc0 = g_WcT2[(2 * k4) * 128 + j];
                float2 wc1 = g_WcT2[(2 * k4 + 1) * 128 + j];
#pragma unroll
                for (int r = 0; r < 8; ++r) {
                    float4 d4 = reinterpret_cast<const float4*>(DS + r * 128)[k4];
                    float4 c4 = reinterpret_cast<const float4*>(CS + r * 128)[k4];
                    ffma2(acc2[r], make_float2(d4.x, d4.y), wd0);
                    ffma2(acc2[r], make_float2(d4.z, d4.w), wd1);
                    ffma2(acc2[r], make_float2(c4.x, c4.y), wc0);
                    ffma2(acc2[r], make_float2(c4.z, c4.w), wc1);
                }
            }
#pragma unroll
            for (int r = 0; r < 8; ++r)
                GS[(g * 8 + r) * 128 + j] = __float2half(acc2[r].x + acc2[r].y);
        }
        __syncthreads();
        // A2: combine 4 partials + b1 -> DP
        for (int o = tid; o < 1024; o += NT) {
            float v = B1[o & 127]
                    + __half2float(GS[o]) + __half2float(GS[1024 + o])
                    + __half2float(GS[2048 + o]) + __half2float(GS[3072 + o]);
            DP[o] = __float2half(v);
        }
        __syncthreads();
        // B: e[p] = sum_j W2[j] * tanh(DP[r][j] + XW[p][j])
        if (tid < R * T) {
            const int p = tid;
            const int r = (p * 1366) >> 16;  // p / 48 for p < 384
            const __half* dp = DP + r * 128;
            const __half* xw = XW + p * XW_S;
            float acc = 0.f;
#pragma unroll 8
            for (int j = 0; j < 128; ++j)
                acc += W2[j] * tanh_fast(__half2float(dp[j]) + __half2float(xw[j]));
            EB[p] = acc;
        }
        __syncthreads();
        // B2: softmax per row (warp per row, 8 warps)
        if (tid < 256) {
            const int w = tid >> 5, l = tid & 31;
            float e0 = EB[w * T + l];
            float e1 = (l < 16) ? EB[w * T + 32 + l] : -3.4e38f;
            float mx = warp_max(fmaxf(e0, e1));
            float x0 = __expf(e0 - mx);
            float x1 = (l < 16) ? __expf(e1 - mx) : 0.f;
            float s  = warp_sum(x0 + x1);
            float inv = __fdividef(1.0f, s);
            EB[w * T + l] = x0 * inv;
            if (l < 16) EB[w * T + 32 + l] = x1 * inv;
        }
        __syncthreads();
        // C: context[r][k] = sum_tt beta[r][tt] * X[r][tt][k]  (rows g and g+4)
        {
            const int k = tid & 127, g = tid >> 7;
            float a0 = 0.f, a1 = 0.f;
#pragma unroll 4
            for (int tt = 0; tt < T; ++tt) {
                a0 += EB[g * T + tt]       * __half2float(XS[(g * T + tt) * 128 + k]);
                a1 += EB[(g + 4) * T + tt] * __half2float(XS[((g + 4) * T + tt) * 128 + k]);
            }
            CT[g * 128 + k]       = __float2half(a0);
            CT[(g + 4) * 128 + k] = __float2half(a1);
        }
        __syncthreads();
        // C2: y_tilde per row (warp per row)
        if (tid < 256) {
            const int w = tid >> 5, l = tid & 31;
            float a = 0.f;
#pragma unroll
            for (int q = 0; q < 4; ++q) {
                int k = l + 32 * q;
                a += FCW[k] * __half2float(CT[w * 128 + k]);
            }
            a = warp_sum(a);
            if (l == 0)
                YT[w] = a + FCW[128] * YP[w * T + t] + FCW[129];
        }
        __syncthreads();
        // D: gates[r][jj] = sum_k Whh[jj][k]*d[r][k] + Wih[jj]*yt[r] + bias[jj]
        {
            const int jj = tid;
            float2 acc2[8];
#pragma unroll
            for (int r = 0; r < 8; ++r) acc2[r] = make_float2(0.f, 0.f);
#pragma unroll 4
            for (int k4 = 0; k4 < 32; ++k4) {
                float2 w0 = g_WhhT2[(2 * k4) * 512 + jj];
                float2 w1 = g_WhhT2[(2 * k4 + 1) * 512 + jj];
#pragma unroll
                for (int r = 0; r < 8; ++r) {
                    float4 d4 = reinterpret_cast<const float4*>(DS + r * 128)[k4];
                    ffma2(acc2[r], make_float2(d4.x, d4.y), w0);
                    ffma2(acc2[r], make_float2(d4.z, d4.w), w1);
                }
            }
            float wih = WIH[jj], bi = BIA[jj];
#pragma unroll
            for (int r = 0; r < 8; ++r)
                GS[r * 512 + jj] = __float2half(acc2[r].x + acc2[r].y + wih * YT[r] + bi);
        }
        __syncthreads();
        // E: LSTM pointwise update
        for (int o = tid; o < 1024; o += NT) {
            const int r = o >> 7, q = o & 127;
            float gi = __half2float(GS[r * 512 + q]);
            float gf = __half2float(GS[r * 512 + 128 + q]);
            float gg = __half2float(GS[r * 512 + 256 + q]);
            float go = __half2float(GS[r * 512 + 384 + q]);
            float cn = sigm(gf) * CS[r * 128 + q] + sigm(gi) * tanh_acc(gg);
            CS[r * 128 + q] = cn;
            DS[r * 128 + q] = sigm(go) * tanh_acc(cn);
        }
        __syncthreads();
    }

    // ---- final: y_pred = fcf . [d, context] + fcf_b;  out += y_pred ----
    if (tid < 256) {
        const int w = tid >> 5, l = tid & 31;
        float a = 0.f;
#pragma unroll
        for (int q = 0; q < 4; ++q) {
            int k = l + 32 * q;
            a += FCF[k] * DS[w * 128 + k]
               + FCF[128 + k] * __half2float(CT[w * 128 + k]);
        }
        a = warp_sum(a);
        if (l == 0) out[b0 + w] += a + FCF[256];
    }
}

// ---------------- launch ----------------
extern "C" void kernel_launch(void* const* d_in, const int* in_sizes, int n_in,
                              void* d_out, int out_size) {
    const float* X     = (const float*)d_in[0];
    const float* yprev = (const float*)d_in[1];
    const float* yskip = (const float*)d_in[2];
    const float* aW1   = (const float*)d_in[3];
    const float* ab1   = (const float*)d_in[4];
    const float* aW2   = (const float*)d_in[5];
    // d_in[6] = attn_b2 (softmax shift-invariant -> unused)
    const float* lWih  = (const float*)d_in[7];
    const float* lWhh  = (const float*)d_in[8];
    const float* lbih  = (const float*)d_in[9];
    const float* lbhh  = (const float*)d_in[10];
    const float* fcW   = (const float*)d_in[11];
    const float* fcb   = (const float*)d_in[12];
    const float* fcfW  = (const float*)d_in[13];
    const float* fcfb  = (const float*)d_in[14];
    const float* gWih  = (const float*)d_in[15];
    const float* gWhh  = (const float*)d_in[16];
    const float* gbih  = (const float*)d_in[17];
    const float* gbhh  = (const float*)d_in[18];
    const float* l1W   = (const float*)d_in[19];
    const float* l1b   = (const float*)d_in[20];
    const float* l2W   = (const float*)d_in[21];
    const float* l2b   = (const float*)d_in[22];
    float* out = (float*)d_out;

    cudaFuncSetAttribute(decoder_kernel, cudaFuncAttributeMaxDynamicSharedMemorySize, SMEM_BYTES);

    // side branch writes out[b] = s_skip + s_linear
    gru_kernel<<<8192 / 128, 128>>>(yskip, yprev, gWih, gWhh, gbih, gbhh,
                                    l1W, l1b, l2W, l2b, out);
    // weight transposes (k-paired float2)
    prep_kernel<<<128, 256>>>(aW1, lWhh);
    // main decoder adds y_pred into out
    decoder_kernel<<<NCTA, NT, SMEM_BYTES>>>(X, yprev, ab1, aW2,
                                             lWih, lbih, lbhh,
                                             fcW, fcb, fcfW, fcfb, out);
}

// round 5
// speedup vs baseline: 1.7978x; 1.1404x over previous
#include <cuda_runtime.h>
#include <cuda_fp16.h>
#include <cstdint>

// ---------------- problem constants ----------------
constexpr int T    = 48;     // Tm1
constexpr int R    = 8;      // rows per CTA
constexpr int NT   = 512;    // threads per CTA
constexpr int NCTA = 8192 / R;   // 1024

// ---------------- device scratch: prepped weights ----------------
__device__ float2  g_WxT2[64 * 128];   // fp32 k-paired (phase 0 only)
__device__ __half2 g_WdH2[64 * 128];   // [k2][j] = (Wd[2k2][j], Wd[2k2+1][j])
__device__ __half2 g_WcH2[64 * 128];
__device__ __half2 g_WhhH2[64 * 512];  // [k2][jj]

// ---------------- helpers ----------------
__device__ __forceinline__ void ffma2(float2& a, float2 x, float2 w) {
    asm("{\n\t"
        ".reg .b64 A, X, W;\n\t"
        "mov.b64 A, {%0, %1};\n\t"
        "mov.b64 X, {%2, %3};\n\t"
        "mov.b64 W, {%4, %5};\n\t"
        "fma.rn.f32x2 A, X, W, A;\n\t"
        "mov.b64 {%0, %1}, A;\n\t"
        "}"
        : "+f"(a.x), "+f"(a.y)
        : "f"(x.x), "f"(x.y), "f"(w.x), "f"(w.y));
}
__device__ __forceinline__ float warp_sum(float v) {
#pragma unroll
    for (int o = 16; o; o >>= 1) v += __shfl_xor_sync(0xffffffffu, v, o);
    return v;
}
__device__ __forceinline__ float warp_max(float v) {
#pragma unroll
    for (int o = 16; o; o >>= 1) v = fmaxf(v, __shfl_xor_sync(0xffffffffu, v, o));
    return v;
}
__device__ __forceinline__ float tanh_fast(float x) {  // MUFU.TANH
    float y;
    asm("tanh.approx.f32 %0, %1;" : "=f"(y) : "f"(x));
    return y;
}
__device__ __forceinline__ float tanh_acc(float x) {
    float e = __expf(2.0f * x);
    return 1.0f - __fdividef(2.0f, e + 1.0f);
}
__device__ __forceinline__ float sigm(float x) {
    return __fdividef(1.0f, 1.0f + __expf(-x));
}

// ---------------- prep: weight transposes / fp16 packing ----------------
__global__ void prep_kernel(const float* __restrict__ W1, const float* __restrict__ Whh) {
    int idx = blockIdx.x * blockDim.x + threadIdx.x;
    if (idx < 32768) {  // 64 k2 x 512 jj
        int k2 = idx >> 9, jj = idx & 511;
        g_WhhH2[idx] = __floats2half2_rn(Whh[jj * 128 + 2 * k2], Whh[jj * 128 + 2 * k2 + 1]);
    }
    if (idx < 8192) {   // 64 k2 x 128 j
        int k2 = idx >> 7, j = idx & 127;
        g_WdH2[idx] = __floats2half2_rn(W1[j * 384 + 2 * k2],       W1[j * 384 + 2 * k2 + 1]);
        g_WcH2[idx] = __floats2half2_rn(W1[j * 384 + 128 + 2 * k2], W1[j * 384 + 128 + 2 * k2 + 1]);
        g_WxT2[idx] = make_float2(W1[j * 384 + 256 + 2 * k2], W1[j * 384 + 256 + 2 * k2 + 1]);
    }
}

// ---------------- GRU + linear side branch: out[b] = s_skip + s_linear ----------------
__global__ __launch_bounds__(128) void gru_kernel(
    const float* __restrict__ y_skip, const float* __restrict__ y_prev,
    const float* __restrict__ gWih, const float* __restrict__ gWhh,
    const float* __restrict__ gbih, const float* __restrict__ gbhh,
    const float* __restrict__ l1W, const float* __restrict__ l1b,
    const float* __restrict__ l2W, const float* __restrict__ l2b,
    float* __restrict__ out)
{
    __shared__ float s[200];
    int tid = threadIdx.x;
    for (int i = tid; i < 15; i += 128) { s[i] = gWih[i]; s[96 + i] = gbih[i]; s[112 + i] = gbhh[i]; }
    for (int i = tid; i < 75; i += 128) s[16 + i] = gWhh[i];
    for (int i = tid; i < 5;  i += 128) s[128 + i] = l1W[i];
    for (int i = tid; i < 48; i += 128) s[144 + i] = l2W[i];
    if (tid == 0) { s[192] = l1b[0]; s[193] = l2b[0]; }
    __syncthreads();

    int b = blockIdx.x * 128 + tid;
    float h[5] = {0.f, 0.f, 0.f, 0.f, 0.f};
#pragma unroll 1
    for (int t = 0; t < 24; t++) {
        float x = y_skip[b * 24 + t];
        float gh[15];
#pragma unroll
        for (int jj = 0; jj < 15; jj++) {
            float a = s[112 + jj];
#pragma unroll
            for (int k = 0; k < 5; k++) a += s[16 + jj * 5 + k] * h[k];
            gh[jj] = a;
        }
#pragma unroll
        for (int q = 0; q < 5; q++) {
            float rr = sigm(s[q] * x + s[96 + q] + gh[q]);
            float zz = sigm(s[5 + q] * x + s[101 + q] + gh[5 + q]);
            float nn = tanh_acc(s[10 + q] * x + s[106 + q] + rr * gh[10 + q]);
            h[q] = (1.0f - zz) * nn + zz * h[q];
        }
    }
    float acc = s[192];
#pragma unroll
    for (int q = 0; q < 5; q++) acc += h[q] * s[128 + q];
    float s2 = s[193];
#pragma unroll 8
    for (int t = 0; t < 48; t++) s2 += y_prev[(size_t)b * 48 + t] * s[144 + t];
    out[b] = acc + s2;
}

// ---------------- SMEM layout (byte offsets) ----------------
constexpr int XW_S   = 130;                 // half stride
constexpr int OB_XS  = 0;                   // half [R*T*128]   98304B
constexpr int OB_XW  = 98304;               // half [R*T*130]   99840B
constexpr int OB_DS  = 198144;              // float [R*128]    4096B
constexpr int OB_CS  = 202240;              // float [R*128]    4096B
constexpr int OB_DP  = 206336;              // half  [R*128]    2048B
constexpr int OB_CT  = 208384;              // half  [R*128]    2048B
constexpr int OB_GS  = 210432;              // half  [4096]     8192B
constexpr int OB_EB  = 218624;              // float [R*T]      1536B
constexpr int OB_YP  = 220160;              // float [R*T]      1536B
constexpr int OB_YT  = 221696;              // float [8]        32B
constexpr int OB_W2  = 221728;              // float [128]      512B
constexpr int OB_B1  = 222240;              // float [128]      512B
constexpr int OB_WIH = 222752;              // float [512]      2048B
constexpr int OB_BIA = 224800;              // float [512]      2048B
constexpr int OB_FCW = 226848;              // float [130]      520B
constexpr int OB_FCF = 227368;              // float [257]      1028B
constexpr int SMEM_BYTES = 228396;

// ---------------- main persistent decoder ----------------
__global__ __launch_bounds__(NT, 1) void decoder_kernel(
    const float* __restrict__ X, const float* __restrict__ yprev,
    const float* __restrict__ ab1, const float* __restrict__ aW2,
    const float* __restrict__ lWih, const float* __restrict__ lbih, const float* __restrict__ lbhh,
    const float* __restrict__ fcW, const float* __restrict__ fcb,
    const float* __restrict__ fcfW, const float* __restrict__ fcfb,
    float* __restrict__ out)
{
    extern __shared__ char smraw[];
    __half* XS = (__half*)(smraw + OB_XS);
    __half* XW = (__half*)(smraw + OB_XW);
    float*  DS = (float*)(smraw + OB_DS);
    float*  CS = (float*)(smraw + OB_CS);
    __half* DP = (__half*)(smraw + OB_DP);
    __half* CT = (__half*)(smraw + OB_CT);
    __half* GS = (__half*)(smraw + OB_GS);
    float*  EB = (float*)(smraw + OB_EB);
    float*  YP = (float*)(smraw + OB_YP);
    float*  YT = (float*)(smraw + OB_YT);
    float*  W2 = (float*)(smraw + OB_W2);
    float*  B1 = (float*)(smraw + OB_B1);
    float*  WIH = (float*)(smraw + OB_WIH);
    float*  BIA = (float*)(smraw + OB_BIA);
    float*  FCW = (float*)(smraw + OB_FCW);
    float*  FCF = (float*)(smraw + OB_FCF);
    float*  XTMP = DS;  // phase-0 staging reuses DS..GS region

    const int tid = threadIdx.x;
    const int b0  = blockIdx.x * R;

    // ---- stage X (fp32 -> fp16), smalls, y_prev ----
    {
        const float2* src = reinterpret_cast<const float2*>(X + (size_t)b0 * T * 128);
        __half2* dst = reinterpret_cast<__half2*>(XS);
        for (int i = tid; i < R * T * 64; i += NT) {
            float2 v = src[i];
            dst[i] = __floats2half2_rn(v.x, v.y);
        }
    }
    for (int i = tid; i < 128; i += NT) { W2[i] = aW2[i]; B1[i] = ab1[i]; }
    for (int i = tid; i < 512; i += NT) { WIH[i] = lWih[i]; BIA[i] = lbih[i] + lbhh[i]; }
    for (int i = tid; i < 129; i += NT) FCW[i] = fcW[i];
    for (int i = tid; i < 256; i += NT) FCF[i] = fcfW[i];
    if (tid == 0) { FCW[129] = fcb[0]; FCF[256] = fcfb[0]; }
    for (int i = tid; i < R * T; i += NT) {
        int r = i / T, tt = i % T;
        YP[i] = yprev[(size_t)(b0 + r) * T + tt];
    }
    __syncthreads();

    // ---- phase 0: XW[p][j] = sum_k X[p][k] * Wx[k][j],  p in [0,384) ----
    {
        const int j = tid & 127, g = tid >> 7;
#pragma unroll 1
        for (int pb = 0; pb < 12; ++pb) {
            for (int e = tid; e < 32 * 128; e += NT) {
                int row = e >> 7, col = e & 127;
                int p = (row >> 3) * 96 + pb * 8 + (row & 7);
                XTMP[e] = __half2float(XS[p * 128 + col]);
            }
            __syncthreads();
            float2 acc2[8];
#pragma unroll
            for (int q = 0; q < 8; ++q) acc2[q] = make_float2(0.f, 0.f);
#pragma unroll 4
            for (int k4 = 0; k4 < 32; ++k4) {
                float2 w0 = g_WxT2[(2 * k4) * 128 + j];
                float2 w1 = g_WxT2[(2 * k4 + 1) * 128 + j];
#pragma unroll
                for (int q = 0; q < 8; ++q) {
                    float4 xv = reinterpret_cast<const float4*>(XTMP + (g * 8 + q) * 128)[k4];
                    ffma2(acc2[q], make_float2(xv.x, xv.y), w0);
                    ffma2(acc2[q], make_float2(xv.z, xv.w), w1);
                }
            }
#pragma unroll
            for (int q = 0; q < 8; ++q) {
                int p = g * 96 + pb * 8 + q;
                XW[p * XW_S + j] = __float2half(acc2[q].x + acc2[q].y);
            }
            __syncthreads();
        }
    }
    // zero states (after phase0, which reused this region)
    for (int i = tid; i < 2 * R * 128; i += NT) DS[i] = 0.0f;  // DS+CS contiguous
    __syncthreads();

    // ---- load Whh column jj=tid into registers (fp16, step-invariant) ----
    __half2 whh[64];
#pragma unroll
    for (int k2 = 0; k2 < 64; ++k2) whh[k2] = g_WhhH2[k2 * 512 + tid];

    // ---- main recurrence ----
#pragma unroll 1
    for (int t = 0; t < T; ++t) {
        // A1: dpart partials, 4-way k-split (g in [0,4)), fp16 streamed weights
        {
            const int j = tid & 127, g = tid >> 7;
            float2 acc2[8];
#pragma unroll
            for (int r = 0; r < 8; ++r) acc2[r] = make_float2(0.f, 0.f);
#pragma unroll 4
            for (int k4o = 0; k4o < 8; ++k4o) {
                const int k4 = (tid >> 7) * 8 + k4o;
                float2 wd0 = __half22float2(g_WdH2[(2 * k4) * 128 + j]);
                float2 wd1 = __half22float2(g_WdH2[(2 * k4 + 1) * 128 + j]);
                float2 wc0 = __half22float2(g_WcH2[(2 * k4) * 128 + j]);
                float2 wc1 = __half22float2(g_WcH2[(2 * k4 + 1) * 128 + j]);
#pragma unroll
                for (int r = 0; r < 8; ++r) {
                    float4 d4 = reinterpret_cast<const float4*>(DS + r * 128)[k4];
                    float4 c4 = reinterpret_cast<const float4*>(CS + r * 128)[k4];
                    ffma2(acc2[r], make_float2(d4.x, d4.y), wd0);
                    ffma2(acc2[r], make_float2(d4.z, d4.w), wd1);
                    ffma2(acc2[r], make_float2(c4.x, c4.y), wc0);
                    ffma2(acc2[r], make_float2(c4.z, c4.w), wc1);
                }
            }
#pragma unroll
            for (int r = 0; r < 8; ++r)
                GS[(g * 8 + r) * 128 + j] = __float2half(acc2[r].x + acc2[r].y);
        }
        __syncthreads();
        // A2: combine 4 partials + b1 -> DP
        for (int o = tid; o < 1024; o += NT) {
            float v = B1[o & 127]
                    + __half2float(GS[o]) + __half2float(GS[1024 + o])
                    + __half2float(GS[2048 + o]) + __half2float(GS[3072 + o]);
            DP[o] = __float2half(v);
        }
        __syncthreads();
        // B: e[p] = sum_j W2[j] * tanh(DP[r][j] + XW[p][j])
        if (tid < R * T) {
            const int p = tid;
            const int r = (p * 1366) >> 16;  // p / 48 for p < 384
            const __half2* dp2 = reinterpret_cast<const __half2*>(DP + r * 128);
            const __half2* xw2 = reinterpret_cast<const __half2*>(XW + p * XW_S);
            float acc = 0.f;
#pragma unroll 8
            for (int j2 = 0; j2 < 64; ++j2) {
                float2 s2 = __half22float2(__hadd2(dp2[j2], xw2[j2]));
                acc += W2[2 * j2]     * tanh_fast(s2.x)
                     + W2[2 * j2 + 1] * tanh_fast(s2.y);
            }
            EB[p] = acc;
        }
        __syncthreads();
        // B2: softmax per row (warp per row, 8 warps)
        if (tid < 256) {
            const int w = tid >> 5, l = tid & 31;
            float e0 = EB[w * T + l];
            float e1 = (l < 16) ? EB[w * T + 32 + l] : -3.4e38f;
            float mx = warp_max(fmaxf(e0, e1));
            float x0 = __expf(e0 - mx);
            float x1 = (l < 16) ? __expf(e1 - mx) : 0.f;
            float s  = warp_sum(x0 + x1);
            float inv = __fdividef(1.0f, s);
            EB[w * T + l] = x0 * inv;
            if (l < 16) EB[w * T + 32 + l] = x1 * inv;
        }
        __syncthreads();
        // C: context[r][k] = sum_tt beta[r][tt] * X[r][tt][k]  (rows g and g+4)
        {
            const int k = tid & 127, g = tid >> 7;
            float a0 = 0.f, a1 = 0.f;
#pragma unroll 4
            for (int tt = 0; tt < T; ++tt) {
                a0 += EB[g * T + tt]       * __half2float(XS[(g * T + tt) * 128 + k]);
                a1 += EB[(g + 4) * T + tt] * __half2float(XS[((g + 4) * T + tt) * 128 + k]);
            }
            CT[g * 128 + k]       = __float2half(a0);
            CT[(g + 4) * 128 + k] = __float2half(a1);
        }
        __syncthreads();
        // C2: y_tilde per row (warp per row)
        if (tid < 256) {
            const int w = tid >> 5, l = tid & 31;
            float a = 0.f;
#pragma unroll
            for (int q = 0; q < 4; ++q) {
                int k = l + 32 * q;
                a += FCW[k] * __half2float(CT[w * 128 + k]);
            }
            a = warp_sum(a);
            if (l == 0)
                YT[w] = a + FCW[128] * YP[w * T + t] + FCW[129];
        }
        __syncthreads();
        // D: gates[r][jj] = sum_k Whh[jj][k]*d[r][k] + Wih[jj]*yt[r] + bias[jj]
        //    Whh column lives in registers (fp16)
        {
            const int jj = tid;
            float2 acc2[8];
#pragma unroll
            for (int r = 0; r < 8; ++r) acc2[r] = make_float2(0.f, 0.f);
#pragma unroll
            for (int k4 = 0; k4 < 32; ++k4) {
                float2 w0 = __half22float2(whh[2 * k4]);
                float2 w1 = __half22float2(whh[2 * k4 + 1]);
#pragma unroll
                for (int r = 0; r < 8; ++r) {
                    float4 d4 = reinterpret_cast<const float4*>(DS + r * 128)[k4];
                    ffma2(acc2[r], make_float2(d4.x, d4.y), w0);
                    ffma2(acc2[r], make_float2(d4.z, d4.w), w1);
                }
            }
            float wih = WIH[jj], bi = BIA[jj];
#pragma unroll
            for (int r = 0; r < 8; ++r)
                GS[r * 512 + jj] = __float2half(acc2[r].x + acc2[r].y + wih * YT[r] + bi);
        }
        __syncthreads();
        // E: LSTM pointwise update
        for (int o = tid; o < 1024; o += NT) {
            const int r = o >> 7, q = o & 127;
            float gi = __half2float(GS[r * 512 + q]);
            float gf = __half2float(GS[r * 512 + 128 + q]);
            float gg = __half2float(GS[r * 512 + 256 + q]);
            float go = __half2float(GS[r * 512 + 384 + q]);
            float cn = sigm(gf) * CS[r * 128 + q] + sigm(gi) * tanh_acc(gg);
            CS[r * 128 + q] = cn;
            DS[r * 128 + q] = sigm(go) * tanh_acc(cn);
        }
        __syncthreads();
    }

    // ---- final: y_pred = fcf . [d, context] + fcf_b;  out += y_pred ----
    if (tid < 256) {
        const int w = tid >> 5, l = tid & 31;
        float a = 0.f;
#pragma unroll
        for (int q = 0; q < 4; ++q) {
            int k = l + 32 * q;
            a += FCF[k] * DS[w * 128 + k]
               + FCF[128 + k] * __half2float(CT[w * 128 + k]);
        }
        a = warp_sum(a);
        if (l == 0) out[b0 + w] += a + FCF[256];
    }
}

// ---------------- launch ----------------
extern "C" void kernel_launch(void* const* d_in, const int* in_sizes, int n_in,
                              void* d_out, int out_size) {
    const float* X     = (const float*)d_in[0];
    const float* yprev = (const float*)d_in[1];
    const float* yskip = (const float*)d_in[2];
    const float* aW1   = (const float*)d_in[3];
    const float* ab1   = (const float*)d_in[4];
    const float* aW2   = (const float*)d_in[5];
    // d_in[6] = attn_b2 (softmax shift-invariant -> unused)
    const float* lWih  = (const float*)d_in[7];
    const float* lWhh  = (const float*)d_in[8];
    const float* lbih  = (const float*)d_in[9];
    const float* lbhh  = (const float*)d_in[10];
    const float* fcW   = (const float*)d_in[11];
    const float* fcb   = (const float*)d_in[12];
    const float* fcfW  = (const float*)d_in[13];
    const float* fcfb  = (const float*)d_in[14];
    const float* gWih  = (const float*)d_in[15];
    const float* gWhh  = (const float*)d_in[16];
    const float* gbih  = (const float*)d_in[17];
    const float* gbhh  = (const float*)d_in[18];
    const float* l1W   = (const float*)d_in[19];
    const float* l1b   = (const float*)d_in[20];
    const float* l2W   = (const float*)d_in[21];
    const float* l2b   = (const float*)d_in[22];
    float* out = (float*)d_out;

    cudaFuncSetAttribute(decoder_kernel, cudaFuncAttributeMaxDynamicSharedMemorySize, SMEM_BYTES);

    // side branch writes out[b] = s_skip + s_linear
    gru_kernel<<<8192 / 128, 128>>>(yskip, yprev, gWih, gWhh, gbih, gbhh,
                                    l1W, l1b, l2W, l2b, out);
    // weight transposes / fp16 packing
    prep_kernel<<<128, 256>>>(aW1, lWhh);
    // main decoder adds y_pred into out
    decoder_kernel<<<NCTA, NT, SMEM_BYTES>>>(X, yprev, ab1, aW2,
                                             lWih, lbih, lbhh,
                                             fcW, fcb, fcfW, fcfb, out);
}

// round 6
// speedup vs baseline: 3.1869x; 1.7726x over previous
#include <cuda_runtime.h>
#include <cuda_fp16.h>
#include <cstdint>

// ---------------- problem constants ----------------
constexpr int T    = 48;     // Tm1
constexpr int R    = 8;      // rows per CTA
constexpr int NT   = 512;    // threads per CTA
constexpr int NCTA = 8192 / R;   // 1024

// ---------------- device scratch: prepped weights ----------------
__device__ float2 g_WxT2[64 * 128];   // fp32 k-paired (phase 0 only)
__device__ uint2  g_WhhFrag[16384];   // [(nt*8+kc)*32+lane] -> (b0,b1) m16n8k16 B frags
__device__ uint2  g_W1Frag[8192];     // [(w*16+kc)*32+lane] -> Wd|Wc frags

// ---------------- helpers ----------------
__device__ __forceinline__ void ffma2(float2& a, float2 x, float2 w) {
    asm("{\n\t"
        ".reg .b64 A, X, W;\n\t"
        "mov.b64 A, {%0, %1};\n\t"
        "mov.b64 X, {%2, %3};\n\t"
        "mov.b64 W, {%4, %5};\n\t"
        "fma.rn.f32x2 A, X, W, A;\n\t"
        "mov.b64 {%0, %1}, A;\n\t"
        "}"
        : "+f"(a.x), "+f"(a.y)
        : "f"(x.x), "f"(x.y), "f"(w.x), "f"(w.y));
}
__device__ __forceinline__ void mma16816(float& d0, float& d1, float& d2, float& d3,
                                         uint32_t a0, uint32_t a2,
                                         uint32_t b0, uint32_t b1) {
    asm volatile(
        "mma.sync.aligned.m16n8k16.row.col.f32.f16.f16.f32 "
        "{%0,%1,%2,%3}, {%4,%5,%6,%7}, {%8,%9}, {%0,%1,%2,%3};\n"
        : "+f"(d0), "+f"(d1), "+f"(d2), "+f"(d3)
        : "r"(a0), "r"(0u), "r"(a2), "r"(0u), "r"(b0), "r"(b1));
}
__device__ __forceinline__ float warp_sum(float v) {
#pragma unroll
    for (int o = 16; o; o >>= 1) v += __shfl_xor_sync(0xffffffffu, v, o);
    return v;
}
__device__ __forceinline__ float warp_max(float v) {
#pragma unroll
    for (int o = 16; o; o >>= 1) v = fmaxf(v, __shfl_xor_sync(0xffffffffu, v, o));
    return v;
}
__device__ __forceinline__ float tanh_fast(float x) {  // MUFU.TANH
    float y;
    asm("tanh.approx.f32 %0, %1;" : "=f"(y) : "f"(x));
    return y;
}
__device__ __forceinline__ float tanh_acc(float x) {
    float e = __expf(2.0f * x);
    return 1.0f - __fdividef(2.0f, e + 1.0f);
}
__device__ __forceinline__ float sigm(float x) {
    return __fdividef(1.0f, 1.0f + __expf(-x));
}
__device__ __forceinline__ uint32_t pack_h2(float a, float b) {
    __half2 h = __floats2half2_rn(a, b);
    return *reinterpret_cast<uint32_t*>(&h);
}

// ---------------- prep: fragment packing ----------------
__global__ void prep_kernel(const float* __restrict__ W1, const float* __restrict__ Whh) {
    int idx = blockIdx.x * blockDim.x + threadIdx.x;
    if (idx < 16384) {  // Whh B-fragments: nt in [0,64), kc in [0,8), lane
        int lane = idx & 31, kc = (idx >> 5) & 7, nt = idx >> 8;
        int n = nt * 8 + (lane >> 2);
        int k0 = kc * 16 + (lane & 3) * 2;
        const float* wr = Whh + n * 128;
        g_WhhFrag[idx] = make_uint2(pack_h2(wr[k0], wr[k0 + 1]),
                                    pack_h2(wr[k0 + 8], wr[k0 + 9]));
    }
    if (idx < 8192) {   // W1 (Wd|Wc) B-fragments: w in [0,16), kc in [0,16), lane
        int lane = idx & 31, kc = (idx >> 5) & 15, w = idx >> 9;
        int j = w * 8 + (lane >> 2);
        int k0 = kc * 16 + (lane & 3) * 2;   // k0 in [0,256) -> first 256 cols of W1 row
        const float* wr = W1 + j * 384;
        g_W1Frag[idx] = make_uint2(pack_h2(wr[k0], wr[k0 + 1]),
                                   pack_h2(wr[k0 + 8], wr[k0 + 9]));
    }
    if (idx < 8192) {   // Wx fp32 k-paired (phase 0)
        int k2 = idx >> 7, j = idx & 127;
        g_WxT2[idx] = make_float2(W1[j * 384 + 256 + 2 * k2], W1[j * 384 + 256 + 2 * k2 + 1]);
    }
}

// ---------------- GRU + linear side branch: out[b] = s_skip + s_linear ----------------
__global__ __launch_bounds__(128) void gru_kernel(
    const float* __restrict__ y_skip, const float* __restrict__ y_prev,
    const float* __restrict__ gWih, const float* __restrict__ gWhh,
    const float* __restrict__ gbih, const float* __restrict__ gbhh,
    const float* __restrict__ l1W, const float* __restrict__ l1b,
    const float* __restrict__ l2W, const float* __restrict__ l2b,
    float* __restrict__ out)
{
    __shared__ float s[200];
    int tid = threadIdx.x;
    for (int i = tid; i < 15; i += 128) { s[i] = gWih[i]; s[96 + i] = gbih[i]; s[112 + i] = gbhh[i]; }
    for (int i = tid; i < 75; i += 128) s[16 + i] = gWhh[i];
    for (int i = tid; i < 5;  i += 128) s[128 + i] = l1W[i];
    for (int i = tid; i < 48; i += 128) s[144 + i] = l2W[i];
    if (tid == 0) { s[192] = l1b[0]; s[193] = l2b[0]; }
    __syncthreads();

    int b = blockIdx.x * 128 + tid;
    float h[5] = {0.f, 0.f, 0.f, 0.f, 0.f};
#pragma unroll 1
    for (int t = 0; t < 24; t++) {
        float x = y_skip[b * 24 + t];
        float gh[15];
#pragma unroll
        for (int jj = 0; jj < 15; jj++) {
            float a = s[112 + jj];
#pragma unroll
            for (int k = 0; k < 5; k++) a += s[16 + jj * 5 + k] * h[k];
            gh[jj] = a;
        }
#pragma unroll
        for (int q = 0; q < 5; q++) {
            float rr = sigm(s[q] * x + s[96 + q] + gh[q]);
            float zz = sigm(s[5 + q] * x + s[101 + q] + gh[5 + q]);
            float nn = tanh_acc(s[10 + q] * x + s[106 + q] + rr * gh[10 + q]);
            h[q] = (1.0f - zz) * nn + zz * h[q];
        }
    }
    float acc = s[192];
#pragma unroll
    for (int q = 0; q < 5; q++) acc += h[q] * s[128 + q];
    float s2 = s[193];
#pragma unroll 8
    for (int t = 0; t < 48; t++) s2 += y_prev[(size_t)b * 48 + t] * s[144 + t];
    out[b] = acc + s2;
}

// ---------------- SMEM layout (byte offsets) ----------------
constexpr int XW_S   = 130;                 // XW half stride
constexpr int DH_S   = 130;                 // DH/CH half stride
constexpr int OB_XS  = 0;                   // half  [R*T*128]   98304
constexpr int OB_XW  = 98304;               // half  [R*T*130]   99840
constexpr int OB_CS  = 198144;              // float [R*128]     4096   (scratch span start)
constexpr int OB_DH  = 202240;              // half  [R*130]     2080
constexpr int OB_CH  = 204320;              // half  [R*130]     2080
constexpr int OB_DP  = 206400;              // half  [R*128]     2048
constexpr int OB_CT  = 208448;              // half  [R*128]     2048
constexpr int OB_GS  = 210496;              // half  [R*512]     8192   (scratch span end 218688)
constexpr int OB_EB  = 218688;              // float [R*T]       1536
constexpr int OB_FX  = 220224;              // half  [R*T]       768
constexpr int OB_YP  = 220992;              // float [R*T]       1536
constexpr int OB_YT  = 222528;              // float [8]         32
constexpr int OB_W2  = 222560;              // float [128]       512
constexpr int OB_B1  = 223072;              // float [128]       512
constexpr int OB_WIH = 223584;              // float [512]       2048
constexpr int OB_BIA = 225632;              // float [512]       2048
constexpr int OB_FCW = 227680;              // float [130]       520
constexpr int OB_FCF = 228200;              // float [257]       1028
constexpr int SMEM_BYTES = 229228;

// ---------------- main persistent decoder ----------------
__global__ __launch_bounds__(NT, 1) void decoder_kernel(
    const float* __restrict__ X, const float* __restrict__ yprev,
    const float* __restrict__ ab1, const float* __restrict__ aW2,
    const float* __restrict__ lWih, const float* __restrict__ lbih, const float* __restrict__ lbhh,
    const float* __restrict__ fcW, const float* __restrict__ fcb,
    const float* __restrict__ fcfW, const float* __restrict__ fcfb,
    float* __restrict__ out)
{
    extern __shared__ char smraw[];
    __half* XS = (__half*)(smraw + OB_XS);
    __half* XW = (__half*)(smraw + OB_XW);
    float*  CS = (float*)(smraw + OB_CS);
    __half* DH = (__half*)(smraw + OB_DH);
    __half* CH = (__half*)(smraw + OB_CH);
    __half* DP = (__half*)(smraw + OB_DP);
    __half* CT = (__half*)(smraw + OB_CT);
    __half* GS = (__half*)(smraw + OB_GS);
    float*  EB = (float*)(smraw + OB_EB);
    __half* FXh = (__half*)(smraw + OB_FX);
    float*  YP = (float*)(smraw + OB_YP);
    float*  YT = (float*)(smraw + OB_YT);
    float*  W2 = (float*)(smraw + OB_W2);
    float*  B1 = (float*)(smraw + OB_B1);
    float*  WIH = (float*)(smraw + OB_WIH);
    float*  BIA = (float*)(smraw + OB_BIA);
    float*  FCW = (float*)(smraw + OB_FCW);
    float*  FCF = (float*)(smraw + OB_FCF);
    float*  XTMP = CS;  // phase-0 staging reuses CS..GS span (20544B >= 16384)

    const int tid  = threadIdx.x;
    const int b0   = blockIdx.x * R;
    const int w    = tid >> 5;        // warp 0..15
    const int lane = tid & 31;
    const int g    = lane >> 2;       // row 0..7 (MMA group)
    const int tg   = lane & 3;        // thread-in-group

    // ---- stage X (fp32 -> fp16), smalls, y_prev ----
    {
        const float2* src = reinterpret_cast<const float2*>(X + (size_t)b0 * T * 128);
        __half2* dst = reinterpret_cast<__half2*>(XS);
        for (int i = tid; i < R * T * 64; i += NT) {
            float2 v = src[i];
            dst[i] = __floats2half2_rn(v.x, v.y);
        }
    }
    for (int i = tid; i < 128; i += NT) { W2[i] = aW2[i]; B1[i] = ab1[i]; }
    for (int i = tid; i < 512; i += NT) { WIH[i] = lWih[i]; BIA[i] = lbih[i] + lbhh[i]; }
    for (int i = tid; i < 129; i += NT) FCW[i] = fcW[i];
    for (int i = tid; i < 256; i += NT) FCF[i] = fcfW[i];
    if (tid == 0) { FCW[129] = fcb[0]; FCF[256] = fcfb[0]; }
    for (int i = tid; i < R * T; i += NT) {
        int r = i / T, tt = i % T;
        YP[i] = yprev[(size_t)(b0 + r) * T + tt];
    }
    __syncthreads();

    // ---- phase 0: XW[p][j] = sum_k X[p][k] * Wx[k][j],  p in [0,384) ----
    {
        const int j = tid & 127, gq = tid >> 7;
#pragma unroll 1
        for (int pb = 0; pb < 12; ++pb) {
            for (int e = tid; e < 32 * 128; e += NT) {
                int row = e >> 7, col = e & 127;
                int p = (row >> 3) * 96 + pb * 8 + (row & 7);
                XTMP[e] = __half2float(XS[p * 128 + col]);
            }
            __syncthreads();
            float2 acc2[8];
#pragma unroll
            for (int q = 0; q < 8; ++q) acc2[q] = make_float2(0.f, 0.f);
#pragma unroll 4
            for (int k4 = 0; k4 < 32; ++k4) {
                float2 w0 = g_WxT2[(2 * k4) * 128 + j];
                float2 w1 = g_WxT2[(2 * k4 + 1) * 128 + j];
#pragma unroll
                for (int q = 0; q < 8; ++q) {
                    float4 xv = reinterpret_cast<const float4*>(XTMP + (gq * 8 + q) * 128)[k4];
                    ffma2(acc2[q], make_float2(xv.x, xv.y), w0);
                    ffma2(acc2[q], make_float2(xv.z, xv.w), w1);
                }
            }
#pragma unroll
            for (int q = 0; q < 8; ++q) {
                int p = gq * 96 + pb * 8 + q;
                XW[p * XW_S + j] = __float2half(acc2[q].x + acc2[q].y);
            }
            __syncthreads();
        }
    }

    // ---- zero states; FX[p] = fc_W . X[p] (y_tilde folding) ----
    for (int i = tid; i < R * 128; i += NT) {
        int r = i >> 7, q = i & 127;
        CS[i] = 0.0f;
        DH[r * DH_S + q] = __float2half(0.f);
        CH[r * DH_S + q] = __float2half(0.f);
    }
    if (tid < R * T) {
        float a = 0.f;
        const __half* xr = XS + tid * 128;
#pragma unroll 8
        for (int k = 0; k < 128; ++k) a += FCW[k] * __half2float(xr[k]);
        FXh[tid] = __float2half(a);
    }

    // ---- preload Whh B-fragments (step-invariant, 64 regs) ----
    uint2 bD[32];
    {
        const uint2* src = g_WhhFrag + (size_t)w * 32 * 32 + lane;
#pragma unroll
        for (int i = 0; i < 32; ++i) bD[i] = src[i * 32];
    }
    __syncthreads();

    // ---- main recurrence ----
#pragma unroll 1
    for (int t = 0; t < T; ++t) {
        // A1 (MMA): dpart[r][j] = sum_k [d|c][r][k] * W1[j][k] + b1[j]  -> DP (half)
        {
            float c0 = 0.f, c1 = 0.f, c2 = 0.f, c3 = 0.f;
#pragma unroll
            for (int kc = 0; kc < 16; ++kc) {
                uint2 bf = g_W1Frag[(w * 16 + kc) * 32 + lane];
                const __half* base = (kc < 8)
                    ? (DH + g * DH_S + kc * 16 + tg * 2)
                    : (CH + g * DH_S + (kc - 8) * 16 + tg * 2);
                uint32_t a0 = *reinterpret_cast<const uint32_t*>(base);
                uint32_t a2 = *reinterpret_cast<const uint32_t*>(base + 8);
                mma16816(c0, c1, c2, c3, a0, a2, bf.x, bf.y);
            }
            int j = w * 8 + tg * 2;
            *reinterpret_cast<__half2*>(DP + g * 128 + j) =
                __floats2half2_rn(c0 + B1[j], c1 + B1[j + 1]);
        }
        __syncthreads();
        // B: e[p] = sum_j W2[j] * tanh(DP[r][j] + XW[p][j])
        if (tid < R * T) {
            const int p = tid;
            const int r = (p * 1366) >> 16;  // p / 48 for p < 384
            const __half2* dp2 = reinterpret_cast<const __half2*>(DP + r * 128);
            const __half2* xw2 = reinterpret_cast<const __half2*>(XW + p * XW_S);
            float acc = 0.f;
#pragma unroll 8
            for (int j2 = 0; j2 < 64; ++j2) {
                float2 s2 = __half22float2(__hadd2(dp2[j2], xw2[j2]));
                acc += W2[2 * j2]     * tanh_fast(s2.x)
                     + W2[2 * j2 + 1] * tanh_fast(s2.y);
            }
            EB[p] = acc;
        }
        __syncthreads();
        // softmax per row + y_tilde via FX (8 warps)
        if (tid < 256) {
            const int wr = tid >> 5, l = tid & 31;
            float e0 = EB[wr * T + l];
            float e1 = (l < 16) ? EB[wr * T + 32 + l] : -3.4e38f;
            float mx = warp_max(fmaxf(e0, e1));
            float x0 = __expf(e0 - mx);
            float x1 = (l < 16) ? __expf(e1 - mx) : 0.f;
            float s  = warp_sum(x0 + x1);
            float inv = __fdividef(1.0f, s);
            float bb0 = x0 * inv, bb1 = x1 * inv;
            EB[wr * T + l] = bb0;
            if (l < 16) EB[wr * T + 32 + l] = bb1;
            float ya = bb0 * __half2float(FXh[wr * T + l]);
            if (l < 16) ya += bb1 * __half2float(FXh[wr * T + 32 + l]);
            ya = warp_sum(ya);
            if (l == 0) YT[wr] = ya + FCW[128] * YP[wr * T + t] + FCW[129];
        }
        __syncthreads();
        // D (MMA): gates[r][jj] = sum_k Whh[jj][k]*d[r][k] + Wih[jj]*yt[r] + bias[jj]
        {
            float acc[4][4];
#pragma unroll
            for (int ti = 0; ti < 4; ++ti)
#pragma unroll
                for (int q = 0; q < 4; ++q) acc[ti][q] = 0.f;
#pragma unroll
            for (int kc = 0; kc < 8; ++kc) {
                const __half* base = DH + g * DH_S + kc * 16 + tg * 2;
                uint32_t a0 = *reinterpret_cast<const uint32_t*>(base);
                uint32_t a2 = *reinterpret_cast<const uint32_t*>(base + 8);
#pragma unroll
                for (int ti = 0; ti < 4; ++ti)
                    mma16816(acc[ti][0], acc[ti][1], acc[ti][2], acc[ti][3],
                             a0, a2, bD[ti * 8 + kc].x, bD[ti * 8 + kc].y);
            }
            float yt = YT[g];
#pragma unroll
            for (int ti = 0; ti < 4; ++ti) {
                int jj = (w * 4 + ti) * 8 + tg * 2;
                float v0 = acc[ti][0] + WIH[jj]     * yt + BIA[jj];
                float v1 = acc[ti][1] + WIH[jj + 1] * yt + BIA[jj + 1];
                *reinterpret_cast<__half2*>(GS + g * 512 + jj) = __floats2half2_rn(v0, v1);
            }
        }
        __syncthreads();
        // E: LSTM pointwise update (c fp32; d,c mirrored to fp16)
        for (int o = tid; o < 1024; o += NT) {
            const int r = o >> 7, q = o & 127;
            float gi = __half2float(GS[r * 512 + q]);
            float gf = __half2float(GS[r * 512 + 128 + q]);
            float gg = __half2float(GS[r * 512 + 256 + q]);
            float go = __half2float(GS[r * 512 + 384 + q]);
            float cn = sigm(gf) * CS[r * 128 + q] + sigm(gi) * tanh_acc(gg);
            CS[r * 128 + q] = cn;
            float dn = sigm(go) * tanh_acc(cn);
            DH[r * DH_S + q] = __float2half(dn);
            CH[r * DH_S + q] = __float2half(cn);
        }
        __syncthreads();
    }

    // ---- final context (only needed once, from last beta) ----
    {
        const int k = tid & 127, g2 = tid >> 7;  // g2 in 0..3
        float a0 = 0.f, a1 = 0.f;
#pragma unroll 4
        for (int tt = 0; tt < T; ++tt) {
            a0 += EB[g2 * T + tt]       * __half2float(XS[(g2 * T + tt) * 128 + k]);
            a1 += EB[(g2 + 4) * T + tt] * __half2float(XS[((g2 + 4) * T + tt) * 128 + k]);
        }
        CT[g2 * 128 + k]       = __float2half(a0);
        CT[(g2 + 4) * 128 + k] = __float2half(a1);
    }
    __syncthreads();
    // ---- final: y_pred = fcf . [d, context] + fcf_b;  out += y_pred ----
    if (tid < 256) {
        const int wr = tid >> 5, l = tid & 31;
        float a = 0.f;
#pragma unroll
        for (int q = 0; q < 4; ++q) {
            int k = l + 32 * q;
            a += FCF[k] * __half2float(DH[wr * DH_S + k])
               + FCF[128 + k] * __half2float(CT[wr * 128 + k]);
        }
        a = warp_sum(a);
        if (l == 0) out[b0 + wr] += a + FCF[256];
    }
}

// ---------------- launch ----------------
extern "C" void kernel_launch(void* const* d_in, const int* in_sizes, int n_in,
                              void* d_out, int out_size) {
    const float* X     = (const float*)d_in[0];
    const float* yprev = (const float*)d_in[1];
    const float* yskip = (const float*)d_in[2];
    const float* aW1   = (const float*)d_in[3];
    const float* ab1   = (const float*)d_in[4];
    const float* aW2   = (const float*)d_in[5];
    // d_in[6] = attn_b2 (softmax shift-invariant -> unused)
    const float* lWih  = (const float*)d_in[7];
    const float* lWhh  = (const float*)d_in[8];
    const float* lbih  = (const float*)d_in[9];
    const float* lbhh  = (const float*)d_in[10];
    const float* fcW   = (const float*)d_in[11];
    const float* fcb   = (const float*)d_in[12];
    const float* fcfW  = (const float*)d_in[13];
    const float* fcfb  = (const float*)d_in[14];
    const float* gWih  = (const float*)d_in[15];
    const float* gWhh  = (const float*)d_in[16];
    const float* gbih  = (const float*)d_in[17];
    const float* gbhh  = (const float*)d_in[18];
    const float* l1W   = (const float*)d_in[19];
    const float* l1b   = (const float*)d_in[20];
    const float* l2W   = (const float*)d_in[21];
    const float* l2b   = (const float*)d_in[22];
    float* out = (float*)d_out;

    cudaFuncSetAttribute(decoder_kernel, cudaFuncAttributeMaxDynamicSharedMemorySize, SMEM_BYTES);

    // side branch writes out[b] = s_skip + s_linear
    gru_kernel<<<8192 / 128, 128>>>(yskip, yprev, gWih, gWhh, gbih, gbhh,
                                    l1W, l1b, l2W, l2b, out);
    // weight fragment packing
    prep_kernel<<<64, 256>>>(aW1, lWhh);
    // main decoder adds y_pred into out
    decoder_kernel<<<NCTA, NT, SMEM_BYTES>>>(X, yprev, ab1, aW2,
                                             lWih, lbih, lbhh,
                                             fcW, fcb, fcfW, fcfb, out);
}

// round 7
// speedup vs baseline: 3.8919x; 1.2212x over previous
#include <cuda_runtime.h>
#include <cuda_fp16.h>
#include <cstdint>

// ---------------- problem constants ----------------
constexpr int T    = 48;     // Tm1
constexpr int R    = 8;      // rows per CTA
constexpr int NT   = 512;    // threads per CTA
constexpr int NCTA = 8192 / R;   // 1024

// ---------------- device scratch: prepped weight fragments ----------------
__device__ uint2 g_WhhFrag[16384];   // [(nt*8+kc)*32+lane] m16n8k16 B frags of Whh
__device__ uint2 g_W1Frag[8192];     // [(w*16+kc)*32+lane] Wd|Wc frags
__device__ uint2 g_WxFrag[4096];     // [(w*8+kc)*32+lane]  Wx frags (phase 0)

// ---------------- helpers ----------------
__device__ __forceinline__ void mma16816(float& d0, float& d1, float& d2, float& d3,
                                         uint32_t a0, uint32_t a2,
                                         uint32_t b0, uint32_t b1) {
    asm volatile(
        "mma.sync.aligned.m16n8k16.row.col.f32.f16.f16.f32 "
        "{%0,%1,%2,%3}, {%4,%5,%6,%7}, {%8,%9}, {%0,%1,%2,%3};\n"
        : "+f"(d0), "+f"(d1), "+f"(d2), "+f"(d3)
        : "r"(a0), "r"(0u), "r"(a2), "r"(0u), "r"(b0), "r"(b1));
}
__device__ __forceinline__ void mma16816_full(float& d0, float& d1, float& d2, float& d3,
                                              uint32_t a0, uint32_t a1, uint32_t a2, uint32_t a3,
                                              uint32_t b0, uint32_t b1) {
    asm volatile(
        "mma.sync.aligned.m16n8k16.row.col.f32.f16.f16.f32 "
        "{%0,%1,%2,%3}, {%4,%5,%6,%7}, {%8,%9}, {%0,%1,%2,%3};\n"
        : "+f"(d0), "+f"(d1), "+f"(d2), "+f"(d3)
        : "r"(a0), "r"(a1), "r"(a2), "r"(a3), "r"(b0), "r"(b1));
}
__device__ __forceinline__ float warp_sum(float v) {
#pragma unroll
    for (int o = 16; o; o >>= 1) v += __shfl_xor_sync(0xffffffffu, v, o);
    return v;
}
__device__ __forceinline__ float warp_max(float v) {
#pragma unroll
    for (int o = 16; o; o >>= 1) v = fmaxf(v, __shfl_xor_sync(0xffffffffu, v, o));
    return v;
}
__device__ __forceinline__ __half2 tanh2_fast(__half2 x) {   // MUFU.TANH f16x2: 2 elems/op
    uint32_t xi = *reinterpret_cast<uint32_t*>(&x);
    uint32_t yi;
    asm("tanh.approx.f16x2 %0, %1;" : "=r"(yi) : "r"(xi));
    return *reinterpret_cast<__half2*>(&yi);
}
__device__ __forceinline__ float tanh_acc(float x) {
    float e = __expf(2.0f * x);
    return 1.0f - __fdividef(2.0f, e + 1.0f);
}
__device__ __forceinline__ float sigm(float x) {
    return __fdividef(1.0f, 1.0f + __expf(-x));
}
__device__ __forceinline__ uint32_t pack_h2(float a, float b) {
    __half2 h = __floats2half2_rn(a, b);
    return *reinterpret_cast<uint32_t*>(&h);
}

// ---------------- prep: fragment packing ----------------
__global__ void prep_kernel(const float* __restrict__ W1, const float* __restrict__ Whh) {
    int idx = blockIdx.x * blockDim.x + threadIdx.x;
    if (idx < 16384) {  // Whh B-fragments: nt in [0,64), kc in [0,8), lane
        int lane = idx & 31, kc = (idx >> 5) & 7, nt = idx >> 8;
        int n = nt * 8 + (lane >> 2);
        int k0 = kc * 16 + (lane & 3) * 2;
        const float* wr = Whh + n * 128;
        g_WhhFrag[idx] = make_uint2(pack_h2(wr[k0], wr[k0 + 1]),
                                    pack_h2(wr[k0 + 8], wr[k0 + 9]));
    }
    if (idx < 8192) {   // W1 (Wd|Wc) B-fragments: w in [0,16), kc in [0,16), lane
        int lane = idx & 31, kc = (idx >> 5) & 15, w = idx >> 9;
        int j = w * 8 + (lane >> 2);
        int k0 = kc * 16 + (lane & 3) * 2;
        const float* wr = W1 + j * 384;
        g_W1Frag[idx] = make_uint2(pack_h2(wr[k0], wr[k0 + 1]),
                                   pack_h2(wr[k0 + 8], wr[k0 + 9]));
    }
    if (idx < 4096) {   // Wx B-fragments: w in [0,16), kc in [0,8), lane
        int lane = idx & 31, kc = (idx >> 5) & 7, w = idx >> 8;
        int j = w * 8 + (lane >> 2);
        int k0 = kc * 16 + (lane & 3) * 2;
        const float* wr = W1 + j * 384 + 256;
        g_WxFrag[idx] = make_uint2(pack_h2(wr[k0], wr[k0 + 1]),
                                   pack_h2(wr[k0 + 8], wr[k0 + 9]));
    }
}

// ---------------- GRU + linear side branch: out[b] = s_skip + s_linear ----------------
__global__ __launch_bounds__(128) void gru_kernel(
    const float* __restrict__ y_skip, const float* __restrict__ y_prev,
    const float* __restrict__ gWih, const float* __restrict__ gWhh,
    const float* __restrict__ gbih, const float* __restrict__ gbhh,
    const float* __restrict__ l1W, const float* __restrict__ l1b,
    const float* __restrict__ l2W, const float* __restrict__ l2b,
    float* __restrict__ out)
{
    __shared__ float s[200];
    int tid = threadIdx.x;
    for (int i = tid; i < 15; i += 128) { s[i] = gWih[i]; s[96 + i] = gbih[i]; s[112 + i] = gbhh[i]; }
    for (int i = tid; i < 75; i += 128) s[16 + i] = gWhh[i];
    for (int i = tid; i < 5;  i += 128) s[128 + i] = l1W[i];
    for (int i = tid; i < 48; i += 128) s[144 + i] = l2W[i];
    if (tid == 0) { s[192] = l1b[0]; s[193] = l2b[0]; }
    __syncthreads();

    int b = blockIdx.x * 128 + tid;
    float h[5] = {0.f, 0.f, 0.f, 0.f, 0.f};
#pragma unroll 1
    for (int t = 0; t < 24; t++) {
        float x = y_skip[b * 24 + t];
        float gh[15];
#pragma unroll
        for (int jj = 0; jj < 15; jj++) {
            float a = s[112 + jj];
#pragma unroll
            for (int k = 0; k < 5; k++) a += s[16 + jj * 5 + k] * h[k];
            gh[jj] = a;
        }
#pragma unroll
        for (int q = 0; q < 5; q++) {
            float rr = sigm(s[q] * x + s[96 + q] + gh[q]);
            float zz = sigm(s[5 + q] * x + s[101 + q] + gh[5 + q]);
            float nn = tanh_acc(s[10 + q] * x + s[106 + q] + rr * gh[10 + q]);
            h[q] = (1.0f - zz) * nn + zz * h[q];
        }
    }
    float acc = s[192];
#pragma unroll
    for (int q = 0; q < 5; q++) acc += h[q] * s[128 + q];
    float s2 = s[193];
#pragma unroll 8
    for (int t = 0; t < 48; t++) s2 += y_prev[(size_t)b * 48 + t] * s[144 + t];
    out[b] = acc + s2;
}

// ---------------- SMEM layout (byte offsets) ----------------
constexpr int XS_S   = 136;                 // XS half stride (68 words: ldmatrix conflict-free)
constexpr int XW_S   = 130;                 // XW half stride (65 words: row reads conflict-free)
constexpr int DH_S   = 130;                 // DH/CH half stride
constexpr int OB_XS  = 0;                   // half  [R*T*136]   104448
constexpr int OB_XW  = 104448;              // half  [R*T*130]   99840  -> 204288
constexpr int OB_CS  = 204288;              // float [R*128]     4096   -> 208384
constexpr int OB_DH  = 208384;              // half  [R*130]     2080   -> 210464
constexpr int OB_CH  = 210464;              // half  [R*130]     2080   -> 212544
constexpr int OB_GS  = 212544;              // half  [R*512]     8192   -> 220736
                                            //   DP aliases GS[0..2048); CT aliases GS+4096
constexpr int OB_EB  = 220736;              // float [R*T]       1536   -> 222272
constexpr int OB_FX  = 222272;              // half  [R*T]       768    -> 223040
constexpr int OB_YP  = 223040;              // float [R*T]       1536   -> 224576
constexpr int OB_YT  = 224576;              // float [8]         32     -> 224608
constexpr int OB_W2  = 224608;              // float [128]       512    -> 225120
constexpr int OB_B1  = 225120;              // float [128]       512    -> 225632
constexpr int OB_WIH = 225632;              // float [512]       2048   -> 227680
constexpr int OB_BIA = 227680;              // float [512]       2048   -> 229728
constexpr int OB_FCW = 229728;              // float [130]       520    -> 230248
constexpr int OB_FCF = 230248;              // float [257]       1028   -> 231276
constexpr int SMEM_BYTES = 231276;          // <= 232448 cap

// ---------------- main persistent decoder ----------------
__global__ __launch_bounds__(NT, 1) void decoder_kernel(
    const float* __restrict__ X, const float* __restrict__ yprev,
    const float* __restrict__ ab1, const float* __restrict__ aW2,
    const float* __restrict__ lWih, const float* __restrict__ lbih, const float* __restrict__ lbhh,
    const float* __restrict__ fcW, const float* __restrict__ fcb,
    const float* __restrict__ fcfW, const float* __restrict__ fcfb,
    float* __restrict__ out)
{
    extern __shared__ char smraw[];
    __half* XS = (__half*)(smraw + OB_XS);
    __half* XW = (__half*)(smraw + OB_XW);
    float*  CS = (float*)(smraw + OB_CS);
    __half* DH = (__half*)(smraw + OB_DH);
    __half* CH = (__half*)(smraw + OB_CH);
    __half* GS = (__half*)(smraw + OB_GS);
    __half* DP = GS;                           // alias: lifetime A1->B, GS lifetime D->E
    __half* CT = (__half*)(smraw + OB_GS + 4096);  // alias: used only after the loop
    float*  EB = (float*)(smraw + OB_EB);
    __half* FXh = (__half*)(smraw + OB_FX);
    float*  YP = (float*)(smraw + OB_YP);
    float*  YT = (float*)(smraw + OB_YT);
    float*  W2 = (float*)(smraw + OB_W2);
    float*  B1 = (float*)(smraw + OB_B1);
    float*  WIH = (float*)(smraw + OB_WIH);
    float*  BIA = (float*)(smraw + OB_BIA);
    float*  FCW = (float*)(smraw + OB_FCW);
    float*  FCF = (float*)(smraw + OB_FCF);

    const int tid  = threadIdx.x;
    const int b0   = blockIdx.x * R;
    const int w    = tid >> 5;        // warp 0..15
    const int lane = tid & 31;
    const int g    = lane >> 2;       // MMA row group 0..7
    const int tg   = lane & 3;        // thread-in-group

    // ---- stage X (fp32 -> fp16, stride 136), smalls, y_prev, zero states ----
    {
        const float2* src = reinterpret_cast<const float2*>(X + (size_t)b0 * T * 128);
        for (int i = tid; i < R * T * 64; i += NT) {
            float2 v = src[i];
            *reinterpret_cast<__half2*>(XS + (i >> 6) * XS_S + (i & 63) * 2) =
                __floats2half2_rn(v.x, v.y);
        }
    }
    for (int i = tid; i < 128; i += NT) { W2[i] = aW2[i]; B1[i] = ab1[i]; }
    for (int i = tid; i < 512; i += NT) { WIH[i] = lWih[i]; BIA[i] = lbih[i] + lbhh[i]; }
    for (int i = tid; i < 129; i += NT) FCW[i] = fcW[i];
    for (int i = tid; i < 256; i += NT) FCF[i] = fcfW[i];
    if (tid == 0) { FCW[129] = fcb[0]; FCF[256] = fcfb[0]; }
    for (int i = tid; i < R * T; i += NT) {
        int r = i / T, tt = i % T;
        YP[i] = yprev[(size_t)(b0 + r) * T + tt];
    }
    for (int i = tid; i < R * 128; i += NT) {
        int r = i >> 7, q = i & 127;
        CS[i] = 0.0f;
        DH[r * DH_S + q] = __float2half(0.f);
        CH[r * DH_S + q] = __float2half(0.f);
    }
    __syncthreads();

    // ---- phase 0 (MMA): XW[p][j] = sum_k X[p][k]*Wx[k][j],  p in [0,384) ----
    {
        uint2 bx[8];
#pragma unroll
        for (int kc = 0; kc < 8; ++kc) bx[kc] = g_WxFrag[(w * 8 + kc) * 32 + lane];
        const int rrow = lane & 15;
        const int rcol = (lane >> 4) * 8;
#pragma unroll 1
        for (int mt = 0; mt < 24; ++mt) {
            float c0 = 0.f, c1 = 0.f, c2 = 0.f, c3 = 0.f;
#pragma unroll
            for (int kc = 0; kc < 8; ++kc) {
                uint32_t a0, a1, a2, a3;
                uint32_t addr = static_cast<uint32_t>(
                    __cvta_generic_to_shared(XS + (mt * 16 + rrow) * XS_S + kc * 16 + rcol));
                asm volatile("ldmatrix.sync.aligned.m8n8.x4.shared.b16 {%0,%1,%2,%3}, [%4];"
                             : "=r"(a0), "=r"(a1), "=r"(a2), "=r"(a3) : "r"(addr));
                mma16816_full(c0, c1, c2, c3, a0, a1, a2, a3, bx[kc].x, bx[kc].y);
            }
            int p0 = mt * 16 + g, p1 = p0 + 8;
            int j = w * 8 + tg * 2;
            *reinterpret_cast<__half2*>(XW + p0 * XW_S + j) = __floats2half2_rn(c0, c1);
            *reinterpret_cast<__half2*>(XW + p1 * XW_S + j) = __floats2half2_rn(c2, c3);
        }
    }

    // ---- FX[p] = fc_W . X[p] (y_tilde folding) ----
    if (tid < R * T) {
        float a = 0.f;
        const __half2* xr = reinterpret_cast<const __half2*>(XS + tid * XS_S);
#pragma unroll 8
        for (int k2 = 0; k2 < 64; ++k2) {
            float2 v = __half22float2(xr[k2]);
            a = fmaf(FCW[2 * k2], v.x, fmaf(FCW[2 * k2 + 1], v.y, a));
        }
        FXh[tid] = __float2half(a);
    }

    // ---- preload Whh B-fragments (step-invariant, 64 regs) ----
    uint2 bD[32];
    {
        const uint2* src = g_WhhFrag + (size_t)w * 32 * 32 + lane;
#pragma unroll
        for (int i = 0; i < 32; ++i) bD[i] = src[i * 32];
    }
    __syncthreads();

    // ---- main recurrence ----
#pragma unroll 1
    for (int t = 0; t < T; ++t) {
        // A1 (MMA): dpart[r][j] = sum_k [d|c][r][k] * W1[j][k] + b1[j]  -> DP (half)
        {
            float c0 = 0.f, c1 = 0.f, c2 = 0.f, c3 = 0.f;
#pragma unroll
            for (int kc = 0; kc < 16; ++kc) {
                uint2 bf = g_W1Frag[(w * 16 + kc) * 32 + lane];
                const __half* base = (kc < 8)
                    ? (DH + g * DH_S + kc * 16 + tg * 2)
                    : (CH + g * DH_S + (kc - 8) * 16 + tg * 2);
                uint32_t a0 = *reinterpret_cast<const uint32_t*>(base);
                uint32_t a2 = *reinterpret_cast<const uint32_t*>(base + 8);
                mma16816(c0, c1, c2, c3, a0, a2, bf.x, bf.y);
            }
            int j = w * 8 + tg * 2;
            *reinterpret_cast<__half2*>(DP + g * 128 + j) =
                __floats2half2_rn(c0 + B1[j], c1 + B1[j + 1]);
        }
        __syncthreads();
        // B: e[p] = sum_j W2[j] * tanh(DP[r][j] + XW[p][j])   (f16x2 tanh: 2/MUFU)
        if (tid < R * T) {
            const int p = tid;
            const int r = (p * 1366) >> 16;  // p / 48 for p < 384
            const __half2* dp2 = reinterpret_cast<const __half2*>(DP + r * 128);
            const __half2* xw2 = reinterpret_cast<const __half2*>(XW + p * XW_S);
            const float2*  w22 = reinterpret_cast<const float2*>(W2);
            float acc = 0.f;
#pragma unroll 8
            for (int j2 = 0; j2 < 64; ++j2) {
                float2 tf = __half22float2(tanh2_fast(__hadd2(dp2[j2], xw2[j2])));
                float2 wv = w22[j2];
                acc = fmaf(wv.x, tf.x, fmaf(wv.y, tf.y, acc));
            }
            EB[p] = acc;
        }
        __syncthreads();
        // softmax per row + y_tilde via FX (8 warps)
        if (tid < 256) {
            const int wr = tid >> 5, l = tid & 31;
            float e0 = EB[wr * T + l];
            float e1 = (l < 16) ? EB[wr * T + 32 + l] : -3.4e38f;
            float mx = warp_max(fmaxf(e0, e1));
            float x0 = __expf(e0 - mx);
            float x1 = (l < 16) ? __expf(e1 - mx) : 0.f;
            float s  = warp_sum(x0 + x1);
            float inv = __fdividef(1.0f, s);
            float bb0 = x0 * inv, bb1 = x1 * inv;
            EB[wr * T + l] = bb0;
            if (l < 16) EB[wr * T + 32 + l] = bb1;
            float ya = bb0 * __half2float(FXh[wr * T + l]);
            if (l < 16) ya += bb1 * __half2float(FXh[wr * T + 32 + l]);
            ya = warp_sum(ya);
            if (l == 0) YT[wr] = ya + FCW[128] * YP[wr * T + t] + FCW[129];
        }
        __syncthreads();
        // D (MMA): gates[r][jj] = sum_k Whh[jj][k]*d[r][k] + Wih[jj]*yt[r] + bias[jj]
        {
            float acc[4][4];
#pragma unroll
            for (int ti = 0; ti < 4; ++ti)
#pragma unroll
                for (int q = 0; q < 4; ++q) acc[ti][q] = 0.f;
#pragma unroll
            for (int kc = 0; kc < 8; ++kc) {
                const __half* base = DH + g * DH_S + kc * 16 + tg * 2;
                uint32_t a0 = *reinterpret_cast<const uint32_t*>(base);
                uint32_t a2 = *reinterpret_cast<const uint32_t*>(base + 8);
#pragma unroll
                for (int ti = 0; ti < 4; ++ti)
                    mma16816(acc[ti][0], acc[ti][1], acc[ti][2], acc[ti][3],
                             a0, a2, bD[ti * 8 + kc].x, bD[ti * 8 + kc].y);
            }
            float yt = YT[g];
#pragma unroll
            for (int ti = 0; ti < 4; ++ti) {
                int jj = (w * 4 + ti) * 8 + tg * 2;
                float v0 = acc[ti][0] + WIH[jj]     * yt + BIA[jj];
                float v1 = acc[ti][1] + WIH[jj + 1] * yt + BIA[jj + 1];
                *reinterpret_cast<__half2*>(GS + g * 512 + jj) = __floats2half2_rn(v0, v1);
            }
        }
        __syncthreads();
        // E: LSTM pointwise update (c fp32; d,c mirrored to fp16)
        for (int o = tid; o < 1024; o += NT) {
            const int r = o >> 7, q = o & 127;
            float gi = __half2float(GS[r * 512 + q]);
            float gf = __half2float(GS[r * 512 + 128 + q]);
            float gg = __half2float(GS[r * 512 + 256 + q]);
            float go = __half2float(GS[r * 512 + 384 + q]);
            float cn = sigm(gf) * CS[r * 128 + q] + sigm(gi) * tanh_acc(gg);
            CS[r * 128 + q] = cn;
            float dn = sigm(go) * tanh_acc(cn);
            DH[r * DH_S + q] = __float2half(dn);
            CH[r * DH_S + q] = __float2half(cn);
        }
        __syncthreads();
    }

    // ---- final context (needed once, from last beta) ----
    {
        const int k = tid & 127, g2 = tid >> 7;  // g2 in 0..3
        float a0 = 0.f, a1 = 0.f;
#pragma unroll 4
        for (int tt = 0; tt < T; ++tt) {
            a0 += EB[g2 * T + tt]       * __half2float(XS[(g2 * T + tt) * XS_S + k]);
            a1 += EB[(g2 + 4) * T + tt] * __half2float(XS[((g2 + 4) * T + tt) * XS_S + k]);
        }
        CT[g2 * 128 + k]       = __float2half(a0);
        CT[(g2 + 4) * 128 + k] = __float2half(a1);
    }
    __syncthreads();
    // ---- final: y_pred = fcf . [d, context] + fcf_b;  out += y_pred ----
    if (tid < 256) {
        const int wr = tid >> 5, l = tid & 31;
        float a = 0.f;
#pragma unroll
        for (int q = 0; q < 4; ++q) {
            int k = l + 32 * q;
            a += FCF[k] * __half2float(DH[wr * DH_S + k])
               + FCF[128 + k] * __half2float(CT[wr * 128 + k]);
        }
        a = warp_sum(a);
        if (l == 0) out[b0 + wr] += a + FCF[256];
    }
}

// ---------------- launch ----------------
extern "C" void kernel_launch(void* const* d_in, const int* in_sizes, int n_in,
                              void* d_out, int out_size) {
    const float* X     = (const float*)d_in[0];
    const float* yprev = (const float*)d_in[1];
    const float* yskip = (const float*)d_in[2];
    const float* aW1   = (const float*)d_in[3];
    const float* ab1   = (const float*)d_in[4];
    const float* aW2   = (const float*)d_in[5];
    // d_in[6] = attn_b2 (softmax shift-invariant -> unused)
    const float* lWih  = (const float*)d_in[7];
    const float* lWhh  = (const float*)d_in[8];
    const float* lbih  = (const float*)d_in[9];
    const float* lbhh  = (const float*)d_in[10];
    const float* fcW   = (const float*)d_in[11];
    const float* fcb   = (const float*)d_in[12];
    const float* fcfW  = (const float*)d_in[13];
    const float* fcfb  = (const float*)d_in[14];
    const float* gWih  = (const float*)d_in[15];
    const float* gWhh  = (const float*)d_in[16];
    const float* gbih  = (const float*)d_in[17];
    const float* gbhh  = (const float*)d_in[18];
    const float* l1W   = (const float*)d_in[19];
    const float* l1b   = (const float*)d_in[20];
    const float* l2W   = (const float*)d_in[21];
    const float* l2b   = (const float*)d_in[22];
    float* out = (float*)d_out;

    cudaFuncSetAttribute(decoder_kernel, cudaFuncAttributeMaxDynamicSharedMemorySize, SMEM_BYTES);

    // side branch writes out[b] = s_skip + s_linear
    gru_kernel<<<8192 / 128, 128>>>(yskip, yprev, gWih, gWhh, gbih, gbhh,
                                    l1W, l1b, l2W, l2b, out);
    // weight fragment packing
    prep_kernel<<<64, 256>>>(aW1, lWhh);
    // main decoder adds y_pred into out
    decoder_kernel<<<NCTA, NT, SMEM_BYTES>>>(X, yprev, ab1, aW2,
                                             lWih, lbih, lbhh,
                                             fcW, fcb, fcfW, fcfb, out);
}

// round 8
// speedup vs baseline: 4.0893x; 1.0507x over previous
#include <cuda_runtime.h>
#include <cuda_fp16.h>
#include <cstdint>

// ---------------- problem constants ----------------
constexpr int T    = 48;     // Tm1
constexpr int R    = 8;      // rows per CTA
constexpr int NT   = 512;    // threads per CTA
constexpr int NCTA = 8192 / R;   // 1024

// ---------------- device scratch: prepped weight fragments ----------------
__device__ uint2 g_WhhFrag[16384];   // [(nt*8+kc)*32+lane] m16n8k16 B frags of Whh
__device__ uint2 g_W1Frag[8192];     // [(w*16+kc)*32+lane] Wd|Wc frags
__device__ uint2 g_WxFrag[4096];     // [(w*8+kc)*32+lane]  Wx frags (phase 0)

// ---------------- helpers ----------------
__device__ __forceinline__ void mma16816(float& d0, float& d1, float& d2, float& d3,
                                         uint32_t a0, uint32_t a2,
                                         uint32_t b0, uint32_t b1) {
    asm volatile(
        "mma.sync.aligned.m16n8k16.row.col.f32.f16.f16.f32 "
        "{%0,%1,%2,%3}, {%4,%5,%6,%7}, {%8,%9}, {%0,%1,%2,%3};\n"
        : "+f"(d0), "+f"(d1), "+f"(d2), "+f"(d3)
        : "r"(a0), "r"(0u), "r"(a2), "r"(0u), "r"(b0), "r"(b1));
}
__device__ __forceinline__ void mma16816_full(float& d0, float& d1, float& d2, float& d3,
                                              uint32_t a0, uint32_t a1, uint32_t a2, uint32_t a3,
                                              uint32_t b0, uint32_t b1) {
    asm volatile(
        "mma.sync.aligned.m16n8k16.row.col.f32.f16.f16.f32 "
        "{%0,%1,%2,%3}, {%4,%5,%6,%7}, {%8,%9}, {%0,%1,%2,%3};\n"
        : "+f"(d0), "+f"(d1), "+f"(d2), "+f"(d3)
        : "r"(a0), "r"(a1), "r"(a2), "r"(a3), "r"(b0), "r"(b1));
}
__device__ __forceinline__ float warp_sum(float v) {
#pragma unroll
    for (int o = 16; o; o >>= 1) v += __shfl_xor_sync(0xffffffffu, v, o);
    return v;
}
__device__ __forceinline__ float warp_max(float v) {
#pragma unroll
    for (int o = 16; o; o >>= 1) v = fmaxf(v, __shfl_xor_sync(0xffffffffu, v, o));
    return v;
}
__device__ __forceinline__ __half2 tanh2_fast(__half2 x) {   // MUFU.TANH f16x2
    uint32_t xi = *reinterpret_cast<uint32_t*>(&x);
    uint32_t yi;
    asm("tanh.approx.f16x2 %0, %1;" : "=r"(yi) : "r"(xi));
    return *reinterpret_cast<__half2*>(&yi);
}
__device__ __forceinline__ float tanh_fast(float x) {        // MUFU.TANH f32
    float y;
    asm("tanh.approx.f32 %0, %1;" : "=f"(y) : "f"(x));
    return y;
}
__device__ __forceinline__ float sigm_fast(float x) {        // 1 MUFU + 1 FMA
    return fmaf(tanh_fast(0.5f * x), 0.5f, 0.5f);
}
__device__ __forceinline__ float tanh_acc(float x) {
    float e = __expf(2.0f * x);
    return 1.0f - __fdividef(2.0f, e + 1.0f);
}
__device__ __forceinline__ float sigm(float x) {
    return __fdividef(1.0f, 1.0f + __expf(-x));
}
__device__ __forceinline__ uint32_t pack_h2(float a, float b) {
    __half2 h = __floats2half2_rn(a, b);
    return *reinterpret_cast<uint32_t*>(&h);
}

// ---------------- prep: fragment packing ----------------
__global__ void prep_kernel(const float* __restrict__ W1, const float* __restrict__ Whh) {
    int idx = blockIdx.x * blockDim.x + threadIdx.x;
    if (idx < 16384) {  // Whh B-fragments
        int lane = idx & 31, kc = (idx >> 5) & 7, nt = idx >> 8;
        int n = nt * 8 + (lane >> 2);
        int k0 = kc * 16 + (lane & 3) * 2;
        const float* wr = Whh + n * 128;
        g_WhhFrag[idx] = make_uint2(pack_h2(wr[k0], wr[k0 + 1]),
                                    pack_h2(wr[k0 + 8], wr[k0 + 9]));
    }
    if (idx < 8192) {   // W1 (Wd|Wc) B-fragments
        int lane = idx & 31, kc = (idx >> 5) & 15, w = idx >> 9;
        int j = w * 8 + (lane >> 2);
        int k0 = kc * 16 + (lane & 3) * 2;
        const float* wr = W1 + j * 384;
        g_W1Frag[idx] = make_uint2(pack_h2(wr[k0], wr[k0 + 1]),
                                   pack_h2(wr[k0 + 8], wr[k0 + 9]));
    }
    if (idx < 4096) {   // Wx B-fragments (phase 0)
        int lane = idx & 31, kc = (idx >> 5) & 7, w = idx >> 8;
        int j = w * 8 + (lane >> 2);
        int k0 = kc * 16 + (lane & 3) * 2;
        const float* wr = W1 + j * 384 + 256;
        g_WxFrag[idx] = make_uint2(pack_h2(wr[k0], wr[k0 + 1]),
                                   pack_h2(wr[k0 + 8], wr[k0 + 9]));
    }
}

// ---------------- GRU + linear side branch: out[b] = s_skip + s_linear ----------------
__global__ __launch_bounds__(128) void gru_kernel(
    const float* __restrict__ y_skip, const float* __restrict__ y_prev,
    const float* __restrict__ gWih, const float* __restrict__ gWhh,
    const float* __restrict__ gbih, const float* __restrict__ gbhh,
    const float* __restrict__ l1W, const float* __restrict__ l1b,
    const float* __restrict__ l2W, const float* __restrict__ l2b,
    float* __restrict__ out)
{
    __shared__ float s[200];
    int tid = threadIdx.x;
    for (int i = tid; i < 15; i += 128) { s[i] = gWih[i]; s[96 + i] = gbih[i]; s[112 + i] = gbhh[i]; }
    for (int i = tid; i < 75; i += 128) s[16 + i] = gWhh[i];
    for (int i = tid; i < 5;  i += 128) s[128 + i] = l1W[i];
    for (int i = tid; i < 48; i += 128) s[144 + i] = l2W[i];
    if (tid == 0) { s[192] = l1b[0]; s[193] = l2b[0]; }
    __syncthreads();

    int b = blockIdx.x * 128 + tid;
    float h[5] = {0.f, 0.f, 0.f, 0.f, 0.f};
#pragma unroll 1
    for (int t = 0; t < 24; t++) {
        float x = y_skip[b * 24 + t];
        float gh[15];
#pragma unroll
        for (int jj = 0; jj < 15; jj++) {
            float a = s[112 + jj];
#pragma unroll
            for (int k = 0; k < 5; k++) a += s[16 + jj * 5 + k] * h[k];
            gh[jj] = a;
        }
#pragma unroll
        for (int q = 0; q < 5; q++) {
            float rr = sigm(s[q] * x + s[96 + q] + gh[q]);
            float zz = sigm(s[5 + q] * x + s[101 + q] + gh[5 + q]);
            float nn = tanh_acc(s[10 + q] * x + s[106 + q] + rr * gh[10 + q]);
            h[q] = (1.0f - zz) * nn + zz * h[q];
        }
    }
    float acc = s[192];
#pragma unroll
    for (int q = 0; q < 5; q++) acc += h[q] * s[128 + q];
    float s2 = s[193];
#pragma unroll 8
    for (int t = 0; t < 48; t++) s2 += y_prev[(size_t)b * 48 + t] * s[144 + t];
    out[b] = acc + s2;
}

// ---------------- SMEM layout (byte offsets) ----------------
constexpr int XS_S   = 136;                 // XS half stride
constexpr int XW_S   = 130;                 // XW half stride
constexpr int DH_S   = 130;                 // DH/CH half stride
constexpr int OB_XS  = 0;                   // half  [R*T*136]   104448
constexpr int OB_XW  = 104448;              // half  [R*T*130]   -> 204288
constexpr int OB_CS  = 204288;              // float [R*128]     -> 208384
constexpr int OB_DH  = 208384;              // half  [R*130]     -> 210464
constexpr int OB_CH  = 210464;              // half  [R*130]     -> 212544
constexpr int OB_GS  = 212544;              // half  [R*512]     -> 220736 (CT aliases GS+4096)
constexpr int OB_DP  = 220736;              // half  [R*128]     -> 222784 (now SEPARATE from GS)
constexpr int OB_EB  = 222784;              // float [R*T]       -> 224320
constexpr int OB_FX  = 224320;              // half  [R*T]       -> 225088
constexpr int OB_YP  = 225088;              // half  [R*T]       -> 225856
constexpr int OB_YT  = 225856;              // float [8]         -> 225888
constexpr int OB_W2  = 225888;              // float [128]       -> 226400
constexpr int OB_B1  = 226400;              // half  [128]       -> 226656
constexpr int OB_WIH = 226656;              // float [512]       -> 228704
constexpr int OB_BIA = 228704;              // float [512]       -> 230752
constexpr int OB_FCW = 230752;              // float [130]       -> 231272
constexpr int OB_FCF = 231272;              // float [257]       -> 232300
constexpr int SMEM_BYTES = 232300;          // <= 232448 cap

// ---------------- main persistent decoder ----------------
__global__ __launch_bounds__(NT, 1) void decoder_kernel(
    const float* __restrict__ X, const float* __restrict__ yprev,
    const float* __restrict__ ab1, const float* __restrict__ aW2,
    const float* __restrict__ lWih, const float* __restrict__ lbih, const float* __restrict__ lbhh,
    const float* __restrict__ fcW, const float* __restrict__ fcb,
    const float* __restrict__ fcfW, const float* __restrict__ fcfb,
    float* __restrict__ out)
{
    extern __shared__ char smraw[];
    __half* XS = (__half*)(smraw + OB_XS);
    __half* XW = (__half*)(smraw + OB_XW);
    float*  CS = (float*)(smraw + OB_CS);
    __half* DH = (__half*)(smraw + OB_DH);
    __half* CH = (__half*)(smraw + OB_CH);
    __half* GS = (__half*)(smraw + OB_GS);
    __half* DP = (__half*)(smraw + OB_DP);
    __half* CT = (__half*)(smraw + OB_GS + 4096);  // epilogue-only alias
    float*  EB = (float*)(smraw + OB_EB);
    __half* FXh = (__half*)(smraw + OB_FX);
    __half* YPh = (__half*)(smraw + OB_YP);
    float*  YT = (float*)(smraw + OB_YT);
    float*  W2 = (float*)(smraw + OB_W2);
    __half* B1h = (__half*)(smraw + OB_B1);
    float*  WIH = (float*)(smraw + OB_WIH);
    float*  BIA = (float*)(smraw + OB_BIA);
    float*  FCW = (float*)(smraw + OB_FCW);
    float*  FCF = (float*)(smraw + OB_FCF);

    const int tid  = threadIdx.x;
    const int b0   = blockIdx.x * R;
    const int w    = tid >> 5;        // warp 0..15
    const int lane = tid & 31;
    const int g    = lane >> 2;       // MMA row group 0..7
    const int tg   = lane & 3;        // thread-in-group

    // ---- stage X (fp32 -> fp16, stride 136), smalls, y_prev, zero states ----
    {
        const float2* src = reinterpret_cast<const float2*>(X + (size_t)b0 * T * 128);
        for (int i = tid; i < R * T * 64; i += NT) {
            float2 v = src[i];
            *reinterpret_cast<__half2*>(XS + (i >> 6) * XS_S + (i & 63) * 2) =
                __floats2half2_rn(v.x, v.y);
        }
    }
    for (int i = tid; i < 128; i += NT) { W2[i] = aW2[i]; B1h[i] = __float2half(ab1[i]); }
    for (int i = tid; i < 512; i += NT) { WIH[i] = lWih[i]; BIA[i] = lbih[i] + lbhh[i]; }
    for (int i = tid; i < 129; i += NT) FCW[i] = fcW[i];
    for (int i = tid; i < 256; i += NT) FCF[i] = fcfW[i];
    if (tid == 0) { FCW[129] = fcb[0]; FCF[256] = fcfb[0]; }
    for (int i = tid; i < R * T; i += NT) {
        int r = i / T, tt = i % T;
        YPh[i] = __float2half(yprev[(size_t)(b0 + r) * T + tt]);
    }
    for (int i = tid; i < R * 128; i += NT) {
        int r = i >> 7, q = i & 127;
        CS[i] = 0.0f;
        DH[r * DH_S + q] = __float2half(0.f);
        CH[r * DH_S + q] = __float2half(0.f);
    }
    __syncthreads();

    // ---- phase 0 (MMA): XW[p][j] = sum_k X[p][k]*Wx[k][j],  p in [0,384) ----
    {
        uint2 bx[8];
#pragma unroll
        for (int kc = 0; kc < 8; ++kc) bx[kc] = g_WxFrag[(w * 8 + kc) * 32 + lane];
        const int rrow = lane & 15;
        const int rcol = (lane >> 4) * 8;
#pragma unroll 1
        for (int mt = 0; mt < 24; ++mt) {
            float c0 = 0.f, c1 = 0.f, c2 = 0.f, c3 = 0.f;
#pragma unroll
            for (int kc = 0; kc < 8; ++kc) {
                uint32_t a0, a1, a2, a3;
                uint32_t addr = static_cast<uint32_t>(
                    __cvta_generic_to_shared(XS + (mt * 16 + rrow) * XS_S + kc * 16 + rcol));
                asm volatile("ldmatrix.sync.aligned.m8n8.x4.shared.b16 {%0,%1,%2,%3}, [%4];"
                             : "=r"(a0), "=r"(a1), "=r"(a2), "=r"(a3) : "r"(addr));
                mma16816_full(c0, c1, c2, c3, a0, a1, a2, a3, bx[kc].x, bx[kc].y);
            }
            int p0 = mt * 16 + g, p1 = p0 + 8;
            int j = w * 8 + tg * 2;
            *reinterpret_cast<__half2*>(XW + p0 * XW_S + j) = __floats2half2_rn(c0, c1);
            *reinterpret_cast<__half2*>(XW + p1 * XW_S + j) = __floats2half2_rn(c2, c3);
        }
    }

    // ---- FX[p] = fc_W . X[p] (y_tilde folding) ----
    if (tid < R * T) {
        float a = 0.f;
        const __half2* xr = reinterpret_cast<const __half2*>(XS + tid * XS_S);
#pragma unroll 8
        for (int k2 = 0; k2 < 64; ++k2) {
            float2 v = __half22float2(xr[k2]);
            a = fmaf(FCW[2 * k2], v.x, fmaf(FCW[2 * k2 + 1], v.y, a));
        }
        FXh[tid] = __float2half(a);
    }

    // ---- preload Whh B-fragments (step-invariant, 64 regs) ----
    uint2 bD[32];
    {
        const uint2* src = g_WhhFrag + (size_t)w * 32 * 32 + lane;
#pragma unroll
        for (int i = 0; i < 32; ++i) bD[i] = src[i * 32];
    }
    __syncthreads();

    // ---- main recurrence (4 barriers/step) ----
#pragma unroll 1
    for (int t = 0; t < T; ++t) {
        // M: A1-MMA (-> DP) and D-MMA partial (-> GS, without yt term) — both read DH/CH only
        {
            // A1: dpart[r][j] = sum_k [d|c][r][k] * W1[j][k] + b1[j]
            float c0 = 0.f, c1 = 0.f, c2 = 0.f, c3 = 0.f;
#pragma unroll
            for (int kc = 0; kc < 16; ++kc) {
                uint2 bf = g_W1Frag[(w * 16 + kc) * 32 + lane];
                const __half* base = (kc < 8)
                    ? (DH + g * DH_S + kc * 16 + tg * 2)
                    : (CH + g * DH_S + (kc - 8) * 16 + tg * 2);
                uint32_t a0 = *reinterpret_cast<const uint32_t*>(base);
                uint32_t a2 = *reinterpret_cast<const uint32_t*>(base + 8);
                mma16816(c0, c1, c2, c3, a0, a2, bf.x, bf.y);
            }
            {
                int j = w * 8 + tg * 2;
                float2 b1v = __half22float2(*reinterpret_cast<const __half2*>(B1h + j));
                *reinterpret_cast<__half2*>(DP + g * 128 + j) =
                    __floats2half2_rn(c0 + b1v.x, c1 + b1v.y);
            }
            // D partial: gates[r][jj] = sum_k Whh[jj][k]*d[r][k] + bias[jj]
            float acc[4][4];
#pragma unroll
            for (int ti = 0; ti < 4; ++ti)
#pragma unroll
                for (int q = 0; q < 4; ++q) acc[ti][q] = 0.f;
#pragma unroll
            for (int kc = 0; kc < 8; ++kc) {
                const __half* base = DH + g * DH_S + kc * 16 + tg * 2;
                uint32_t a0 = *reinterpret_cast<const uint32_t*>(base);
                uint32_t a2 = *reinterpret_cast<const uint32_t*>(base + 8);
#pragma unroll
                for (int ti = 0; ti < 4; ++ti)
                    mma16816(acc[ti][0], acc[ti][1], acc[ti][2], acc[ti][3],
                             a0, a2, bD[ti * 8 + kc].x, bD[ti * 8 + kc].y);
            }
#pragma unroll
            for (int ti = 0; ti < 4; ++ti) {
                int jj = (w * 4 + ti) * 8 + tg * 2;
                *reinterpret_cast<__half2*>(GS + g * 512 + jj) =
                    __floats2half2_rn(acc[ti][0] + BIA[jj], acc[ti][1] + BIA[jj + 1]);
            }
        }
        __syncthreads();
        // B: e[p] = sum_j W2[j] * tanh(DP[r][j] + XW[p][j])   (f16x2 tanh)
        if (tid < R * T) {
            const int p = tid;
            const int r = (p * 1366) >> 16;  // p / 48 for p < 384
            const __half2* dp2 = reinterpret_cast<const __half2*>(DP + r * 128);
            const __half2* xw2 = reinterpret_cast<const __half2*>(XW + p * XW_S);
            const float2*  w22 = reinterpret_cast<const float2*>(W2);
            float acc = 0.f;
#pragma unroll 8
            for (int j2 = 0; j2 < 64; ++j2) {
                float2 tf = __half22float2(tanh2_fast(__hadd2(dp2[j2], xw2[j2])));
                float2 wv = w22[j2];
                acc = fmaf(wv.x, tf.x, fmaf(wv.y, tf.y, acc));
            }
            EB[p] = acc;
        }
        __syncthreads();
        // softmax per row + y_tilde via FX (8 warps)
        if (tid < 256) {
            const int wr = tid >> 5, l = tid & 31;
            float e0 = EB[wr * T + l];
            float e1 = (l < 16) ? EB[wr * T + 32 + l] : -3.4e38f;
            float mx = warp_max(fmaxf(e0, e1));
            float x0 = __expf(e0 - mx);
            float x1 = (l < 16) ? __expf(e1 - mx) : 0.f;
            float s  = warp_sum(x0 + x1);
            float inv = __fdividef(1.0f, s);
            float bb0 = x0 * inv, bb1 = x1 * inv;
            EB[wr * T + l] = bb0;
            if (l < 16) EB[wr * T + 32 + l] = bb1;
            float ya = bb0 * __half2float(FXh[wr * T + l]);
            if (l < 16) ya += bb1 * __half2float(FXh[wr * T + 32 + l]);
            ya = warp_sum(ya);
            if (l == 0) YT[wr] = ya + FCW[128] * __half2float(YPh[wr * T + t]) + FCW[129];
        }
        __syncthreads();
        // E: LSTM pointwise update; fold in Wih*yt here (fast activations)
        for (int o = tid; o < 1024; o += NT) {
            const int r = o >> 7, q = o & 127;
            float yt = YT[r];
            float gi = __half2float(GS[r * 512 + q])       + WIH[q]       * yt;
            float gf = __half2float(GS[r * 512 + 128 + q]) + WIH[128 + q] * yt;
            float gg = __half2float(GS[r * 512 + 256 + q]) + WIH[256 + q] * yt;
            float go = __half2float(GS[r * 512 + 384 + q]) + WIH[384 + q] * yt;
            float cn = sigm_fast(gf) * CS[r * 128 + q] + sigm_fast(gi) * tanh_fast(gg);
            CS[r * 128 + q] = cn;
            float dn = sigm_fast(go) * tanh_fast(cn);
            DH[r * DH_S + q] = __float2half(dn);
            CH[r * DH_S + q] = __float2half(cn);
        }
        __syncthreads();
    }

    // ---- final context (needed once, from last beta) ----
    {
        const int k = tid & 127, g2 = tid >> 7;  // g2 in 0..3
        float a0 = 0.f, a1 = 0.f;
#pragma unroll 4
        for (int tt = 0; tt < T; ++tt) {
            a0 += EB[g2 * T + tt]       * __half2float(XS[(g2 * T + tt) * XS_S + k]);
            a1 += EB[(g2 + 4) * T + tt] * __half2float(XS[((g2 + 4) * T + tt) * XS_S + k]);
        }
        CT[g2 * 128 + k]       = __float2half(a0);
        CT[(g2 + 4) * 128 + k] = __float2half(a1);
    }
    __syncthreads();
    // ---- final: y_pred = fcf . [d, context] + fcf_b;  out += y_pred ----
    if (tid < 256) {
        const int wr = tid >> 5, l = tid & 31;
        float a = 0.f;
#pragma unroll
        for (int q = 0; q < 4; ++q) {
            int k = l + 32 * q;
            a += FCF[k] * __half2float(DH[wr * DH_S + k])
               + FCF[128 + k] * __half2float(CT[wr * 128 + k]);
        }
        a = warp_sum(a);
        if (l == 0) out[b0 + wr] += a + FCF[256];
    }
}

// ---------------- launch ----------------
extern "C" void kernel_launch(void* const* d_in, const int* in_sizes, int n_in,
                              void* d_out, int out_size) {
    const float* X     = (const float*)d_in[0];
    const float* yprev = (const float*)d_in[1];
    const float* yskip = (const float*)d_in[2];
    const float* aW1   = (const float*)d_in[3];
    const float* ab1   = (const float*)d_in[4];
    const float* aW2   = (const float*)d_in[5];
    // d_in[6] = attn_b2 (softmax shift-invariant -> unused)
    const float* lWih  = (const float*)d_in[7];
    const float* lWhh  = (const float*)d_in[8];
    const float* lbih  = (const float*)d_in[9];
    const float* lbhh  = (const float*)d_in[10];
    const float* fcW   = (const float*)d_in[11];
    const float* fcb   = (const float*)d_in[12];
    const float* fcfW  = (const float*)d_in[13];
    const float* fcfb  = (const float*)d_in[14];
    const float* gWih  = (const float*)d_in[15];
    const float* gWhh  = (const float*)d_in[16];
    const float* gbih  = (const float*)d_in[17];
    const float* gbhh  = (const float*)d_in[18];
    const float* l1W   = (const float*)d_in[19];
    const float* l1b   = (const float*)d_in[20];
    const float* l2W   = (const float*)d_in[21];
    const float* l2b   = (const float*)d_in[22];
    float* out = (float*)d_out;

    cudaFuncSetAttribute(decoder_kernel, cudaFuncAttributeMaxDynamicSharedMemorySize, SMEM_BYTES);

    // side branch writes out[b] = s_skip + s_linear
    gru_kernel<<<8192 / 128, 128>>>(yskip, yprev, gWih, gWhh, gbih, gbhh,
                                    l1W, l1b, l2W, l2b, out);
    // weight fragment packing
    prep_kernel<<<64, 256>>>(aW1, lWhh);
    // main decoder adds y_pred into out
    decoder_kernel<<<NCTA, NT, SMEM_BYTES>>>(X, yprev, ab1, aW2,
                                             lWih, lbih, lbhh,
                                             fcW, fcb, fcfW, fcfb, out);
}

// round 9
// speedup vs baseline: 5.0545x; 1.2360x over previous
#include <cuda_runtime.h>
#include <cuda_fp16.h>
#include <cstdint>

// ---------------- problem constants ----------------
constexpr int T    = 48;     // Tm1
constexpr int R    = 8;      // rows per CTA
constexpr int NT   = 512;    // threads per CTA
constexpr int NCTA = 8192 / R;   // 1024

// ---------------- device scratch: prepped weight fragments ----------------
__device__ uint2 g_WhhFrag[16384];   // [(nt*8+kc)*32+lane] m16n8k16 B frags of Whh
__device__ uint2 g_W1Frag[8192];     // [(w*16+kc)*32+lane] Wd|Wc frags
__device__ uint2 g_WxFrag[4096];     // [(w*8+kc)*32+lane]  Wx frags (phase 0)

// ---------------- helpers ----------------
__device__ __forceinline__ void mma16816(float& d0, float& d1, float& d2, float& d3,
                                         uint32_t a0, uint32_t a2,
                                         uint32_t b0, uint32_t b1) {
    asm volatile(
        "mma.sync.aligned.m16n8k16.row.col.f32.f16.f16.f32 "
        "{%0,%1,%2,%3}, {%4,%5,%6,%7}, {%8,%9}, {%0,%1,%2,%3};\n"
        : "+f"(d0), "+f"(d1), "+f"(d2), "+f"(d3)
        : "r"(a0), "r"(0u), "r"(a2), "r"(0u), "r"(b0), "r"(b1));
}
__device__ __forceinline__ void mma16816_full(float& d0, float& d1, float& d2, float& d3,
                                              uint32_t a0, uint32_t a1, uint32_t a2, uint32_t a3,
                                              uint32_t b0, uint32_t b1) {
    asm volatile(
        "mma.sync.aligned.m16n8k16.row.col.f32.f16.f16.f32 "
        "{%0,%1,%2,%3}, {%4,%5,%6,%7}, {%8,%9}, {%0,%1,%2,%3};\n"
        : "+f"(d0), "+f"(d1), "+f"(d2), "+f"(d3)
        : "r"(a0), "r"(a1), "r"(a2), "r"(a3), "r"(b0), "r"(b1));
}
__device__ __forceinline__ float warp_sum(float v) {
#pragma unroll
    for (int o = 16; o; o >>= 1) v += __shfl_xor_sync(0xffffffffu, v, o);
    return v;
}
__device__ __forceinline__ __half2 tanh2_fast(__half2 x) {   // MUFU.TANH f16x2
    uint32_t xi = *reinterpret_cast<uint32_t*>(&x);
    uint32_t yi;
    asm("tanh.approx.f16x2 %0, %1;" : "=r"(yi) : "r"(xi));
    return *reinterpret_cast<__half2*>(&yi);
}
__device__ __forceinline__ float2 tanh2f(float a, float b) { // pack->tanh2->unpack
    __half2 h = tanh2_fast(__floats2half2_rn(a, b));
    return __half22float2(h);
}
__device__ __forceinline__ float2 sigm2f(float a, float b) { // sigmoid pair via tanh2
    float2 t = tanh2f(0.5f * a, 0.5f * b);
    return make_float2(fmaf(t.x, 0.5f, 0.5f), fmaf(t.y, 0.5f, 0.5f));
}
__device__ __forceinline__ float tanh_acc(float x) {
    float e = __expf(2.0f * x);
    return 1.0f - __fdividef(2.0f, e + 1.0f);
}
__device__ __forceinline__ float sigm(float x) {
    return __fdividef(1.0f, 1.0f + __expf(-x));
}
__device__ __forceinline__ uint32_t pack_h2(float a, float b) {
    __half2 h = __floats2half2_rn(a, b);
    return *reinterpret_cast<uint32_t*>(&h);
}

// ---------------- prep: fragment packing ----------------
__global__ void prep_kernel(const float* __restrict__ W1, const float* __restrict__ Whh) {
    int idx = blockIdx.x * blockDim.x + threadIdx.x;
    if (idx < 16384) {  // Whh B-fragments
        int lane = idx & 31, kc = (idx >> 5) & 7, nt = idx >> 8;
        int n = nt * 8 + (lane >> 2);
        int k0 = kc * 16 + (lane & 3) * 2;
        const float* wr = Whh + n * 128;
        g_WhhFrag[idx] = make_uint2(pack_h2(wr[k0], wr[k0 + 1]),
                                    pack_h2(wr[k0 + 8], wr[k0 + 9]));
    }
    if (idx < 8192) {   // W1 (Wd|Wc) B-fragments
        int lane = idx & 31, kc = (idx >> 5) & 15, w = idx >> 9;
        int j = w * 8 + (lane >> 2);
        int k0 = kc * 16 + (lane & 3) * 2;
        const float* wr = W1 + j * 384;
        g_W1Frag[idx] = make_uint2(pack_h2(wr[k0], wr[k0 + 1]),
                                   pack_h2(wr[k0 + 8], wr[k0 + 9]));
    }
    if (idx < 4096) {   // Wx B-fragments (phase 0)
        int lane = idx & 31, kc = (idx >> 5) & 7, w = idx >> 8;
        int j = w * 8 + (lane >> 2);
        int k0 = kc * 16 + (lane & 3) * 2;
        const float* wr = W1 + j * 384 + 256;
        g_WxFrag[idx] = make_uint2(pack_h2(wr[k0], wr[k0 + 1]),
                                   pack_h2(wr[k0 + 8], wr[k0 + 9]));
    }
}

// ---------------- GRU + linear side branch: out[b] = s_skip + s_linear ----------------
__global__ __launch_bounds__(128) void gru_kernel(
    const float* __restrict__ y_skip, const float* __restrict__ y_prev,
    const float* __restrict__ gWih, const float* __restrict__ gWhh,
    const float* __restrict__ gbih, const float* __restrict__ gbhh,
    const float* __restrict__ l1W, const float* __restrict__ l1b,
    const float* __restrict__ l2W, const float* __restrict__ l2b,
    float* __restrict__ out)
{
    __shared__ float s[200];
    int tid = threadIdx.x;
    for (int i = tid; i < 15; i += 128) { s[i] = gWih[i]; s[96 + i] = gbih[i]; s[112 + i] = gbhh[i]; }
    for (int i = tid; i < 75; i += 128) s[16 + i] = gWhh[i];
    for (int i = tid; i < 5;  i += 128) s[128 + i] = l1W[i];
    for (int i = tid; i < 48; i += 128) s[144 + i] = l2W[i];
    if (tid == 0) { s[192] = l1b[0]; s[193] = l2b[0]; }
    __syncthreads();

    int b = blockIdx.x * 128 + tid;
    float h[5] = {0.f, 0.f, 0.f, 0.f, 0.f};
#pragma unroll 1
    for (int t = 0; t < 24; t++) {
        float x = y_skip[b * 24 + t];
        float gh[15];
#pragma unroll
        for (int jj = 0; jj < 15; jj++) {
            float a = s[112 + jj];
#pragma unroll
            for (int k = 0; k < 5; k++) a += s[16 + jj * 5 + k] * h[k];
            gh[jj] = a;
        }
#pragma unroll
        for (int q = 0; q < 5; q++) {
            float rr = sigm(s[q] * x + s[96 + q] + gh[q]);
            float zz = sigm(s[5 + q] * x + s[101 + q] + gh[5 + q]);
            float nn = tanh_acc(s[10 + q] * x + s[106 + q] + rr * gh[10 + q]);
            h[q] = (1.0f - zz) * nn + zz * h[q];
        }
    }
    float acc = s[192];
#pragma unroll
    for (int q = 0; q < 5; q++) acc += h[q] * s[128 + q];
    float s2 = s[193];
#pragma unroll 8
    for (int t = 0; t < 48; t++) s2 += y_prev[(size_t)b * 48 + t] * s[144 + t];
    out[b] = acc + s2;
}

// ---------------- SMEM layout (byte offsets) ----------------
constexpr int XS_S   = 136;                 // XS half stride
constexpr int XW_S   = 130;                 // XW half stride
constexpr int DH_S   = 130;                 // DH/CH half stride
constexpr int OB_XS  = 0;                   // half  [R*T*136]   -> 104448
constexpr int OB_XW  = 104448;              // half  [R*T*130]   -> 204288
constexpr int OB_CS  = 204288;              // float [R*128]     -> 208384
constexpr int OB_DH  = 208384;              // half  [R*130]     -> 210464
constexpr int OB_CH  = 210464;              // half  [R*130]     -> 212544
constexpr int OB_GS  = 212544;              // half  [R*512]     -> 220736 (CT aliases GS+4096)
constexpr int OB_DP  = 220736;              // half  [R*128]     -> 222784
constexpr int OB_EB2 = 222784;              // float2[R*T]       -> 225856  (exp, exp*FX)
constexpr int OB_FX  = 225856;              // half  [R*T]       -> 226624
constexpr int OB_YP  = 226624;              // half  [R*T]       -> 227392
constexpr int OB_YT  = 227392;              // float [8]         -> 227424  (epilogue INV)
constexpr int OB_W2  = 227424;              // half  [128]       -> 227680
constexpr int OB_B1  = 227680;              // half  [128]       -> 227936
constexpr int OB_WIH = 227936;              // half  [512]       -> 228960
constexpr int OB_BIA = 228960;              // half  [512]       -> 229984
constexpr int OB_FCW = 229984;              // float [130]       -> 230504
constexpr int OB_FCF = 230504;              // float [257]       -> 231532
constexpr int SMEM_BYTES = 231532;          // <= 232448 cap

// ---------------- main persistent decoder ----------------
__global__ __launch_bounds__(NT, 1) void decoder_kernel(
    const float* __restrict__ X, const float* __restrict__ yprev,
    const float* __restrict__ ab1, const float* __restrict__ aW2,
    const float* __restrict__ lWih, const float* __restrict__ lbih, const float* __restrict__ lbhh,
    const float* __restrict__ fcW, const float* __restrict__ fcb,
    const float* __restrict__ fcfW, const float* __restrict__ fcfb,
    float* __restrict__ out)
{
    extern __shared__ char smraw[];
    __half* XS = (__half*)(smraw + OB_XS);
    __half* XW = (__half*)(smraw + OB_XW);
    float*  CS = (float*)(smraw + OB_CS);
    __half* DH = (__half*)(smraw + OB_DH);
    __half* CH = (__half*)(smraw + OB_CH);
    __half* GS = (__half*)(smraw + OB_GS);
    __half* DP = (__half*)(smraw + OB_DP);
    __half* CT = (__half*)(smraw + OB_GS + 4096);  // epilogue-only alias
    float2* EB2 = (float2*)(smraw + OB_EB2);
    __half* FXh = (__half*)(smraw + OB_FX);
    __half* YPh = (__half*)(smraw + OB_YP);
    float*  YT = (float*)(smraw + OB_YT);          // epilogue inv-sums
    __half* W2h = (__half*)(smraw + OB_W2);
    __half* B1h = (__half*)(smraw + OB_B1);
    __half* WIHh = (__half*)(smraw + OB_WIH);
    __half* BIAh = (__half*)(smraw + OB_BIA);
    float*  FCW = (float*)(smraw + OB_FCW);
    float*  FCF = (float*)(smraw + OB_FCF);

    const int tid  = threadIdx.x;
    const int b0   = blockIdx.x * R;
    const int w    = tid >> 5;        // warp 0..15
    const int lane = tid & 31;
    const int g    = lane >> 2;       // MMA row group 0..7
    const int tg   = lane & 3;        // thread-in-group

    // ---- stage X (fp32 -> fp16, stride 136), smalls, y_prev, zero states ----
    {
        const float2* src = reinterpret_cast<const float2*>(X + (size_t)b0 * T * 128);
        for (int i = tid; i < R * T * 64; i += NT) {
            float2 v = src[i];
            *reinterpret_cast<__half2*>(XS + (i >> 6) * XS_S + (i & 63) * 2) =
                __floats2half2_rn(v.x, v.y);
        }
    }
    for (int i = tid; i < 128; i += NT) { W2h[i] = __float2half(aW2[i]); B1h[i] = __float2half(ab1[i]); }
    for (int i = tid; i < 512; i += NT) {
        WIHh[i] = __float2half(lWih[i]);
        BIAh[i] = __float2half(lbih[i] + lbhh[i]);
    }
    for (int i = tid; i < 129; i += NT) FCW[i] = fcW[i];
    for (int i = tid; i < 256; i += NT) FCF[i] = fcfW[i];
    if (tid == 0) { FCW[129] = fcb[0]; FCF[256] = fcfb[0]; }
    for (int i = tid; i < R * T; i += NT) {
        int r = i / T, tt = i % T;
        YPh[i] = __float2half(yprev[(size_t)(b0 + r) * T + tt]);
    }
    for (int i = tid; i < R * 128; i += NT) {
        int r = i >> 7, q = i & 127;
        CS[i] = 0.0f;
        DH[r * DH_S + q] = __float2half(0.f);
        CH[r * DH_S + q] = __float2half(0.f);
    }
    __syncthreads();

    // ---- phase 0 (MMA): XW[p][j] = sum_k X[p][k]*Wx[k][j],  p in [0,384) ----
    {
        uint2 bx[8];
#pragma unroll
        for (int kc = 0; kc < 8; ++kc) bx[kc] = g_WxFrag[(w * 8 + kc) * 32 + lane];
        const int rrow = lane & 15;
        const int rcol = (lane >> 4) * 8;
#pragma unroll 1
        for (int mt = 0; mt < 24; ++mt) {
            float c0 = 0.f, c1 = 0.f, c2 = 0.f, c3 = 0.f;
#pragma unroll
            for (int kc = 0; kc < 8; ++kc) {
                uint32_t a0, a1, a2, a3;
                uint32_t addr = static_cast<uint32_t>(
                    __cvta_generic_to_shared(XS + (mt * 16 + rrow) * XS_S + kc * 16 + rcol));
                asm volatile("ldmatrix.sync.aligned.m8n8.x4.shared.b16 {%0,%1,%2,%3}, [%4];"
                             : "=r"(a0), "=r"(a1), "=r"(a2), "=r"(a3) : "r"(addr));
                mma16816_full(c0, c1, c2, c3, a0, a1, a2, a3, bx[kc].x, bx[kc].y);
            }
            int p0 = mt * 16 + g, p1 = p0 + 8;
            int j = w * 8 + tg * 2;
            *reinterpret_cast<__half2*>(XW + p0 * XW_S + j) = __floats2half2_rn(c0, c1);
            *reinterpret_cast<__half2*>(XW + p1 * XW_S + j) = __floats2half2_rn(c2, c3);
        }
    }

    // ---- FX[p] = fc_W . X[p] (y_tilde folding) ----
    if (tid < R * T) {
        float a = 0.f;
        const __half2* xr = reinterpret_cast<const __half2*>(XS + tid * XS_S);
#pragma unroll 8
        for (int k2 = 0; k2 < 64; ++k2) {
            float2 v = __half22float2(xr[k2]);
            a = fmaf(FCW[2 * k2], v.x, fmaf(FCW[2 * k2 + 1], v.y, a));
        }
        FXh[tid] = __float2half(a);
    }

    // ---- preload Whh B-fragments (step-invariant, 64 regs) ----
    uint2 bD[32];
    {
        const uint2* src = g_WhhFrag + (size_t)w * 32 * 32 + lane;
#pragma unroll
        for (int i = 0; i < 32; ++i) bD[i] = src[i * 32];
    }
    __syncthreads();

    // ---- main recurrence (3 barriers/step) ----
#pragma unroll 1
    for (int t = 0; t < T; ++t) {
        // M: A1-MMA (-> DP, two 8-deep chains) and D-MMA partial (-> GS)
        {
            float c0 = 0.f, c1 = 0.f, c2 = 0.f, c3 = 0.f;   // A1 chain 1 (DH)
            float e0 = 0.f, e1 = 0.f, e2 = 0.f, e3 = 0.f;   // A1 chain 2 (CH)
            float acc[4][4];
#pragma unroll
            for (int ti = 0; ti < 4; ++ti)
#pragma unroll
                for (int q = 0; q < 4; ++q) acc[ti][q] = 0.f;
            // kc 0..7: DH frags feed A1-chain1 and all of D
#pragma unroll
            for (int kc = 0; kc < 8; ++kc) {
                const __half* base = DH + g * DH_S + kc * 16 + tg * 2;
                uint32_t a0 = *reinterpret_cast<const uint32_t*>(base);
                uint32_t a2 = *reinterpret_cast<const uint32_t*>(base + 8);
                uint2 bf = g_W1Frag[(w * 16 + kc) * 32 + lane];
                mma16816(c0, c1, c2, c3, a0, a2, bf.x, bf.y);
#pragma unroll
                for (int ti = 0; ti < 4; ++ti)
                    mma16816(acc[ti][0], acc[ti][1], acc[ti][2], acc[ti][3],
                             a0, a2, bD[ti * 8 + kc].x, bD[ti * 8 + kc].y);
            }
            // kc 8..15: CH frags feed A1-chain2
#pragma unroll
            for (int kc = 0; kc < 8; ++kc) {
                const __half* base = CH + g * DH_S + kc * 16 + tg * 2;
                uint32_t a0 = *reinterpret_cast<const uint32_t*>(base);
                uint32_t a2 = *reinterpret_cast<const uint32_t*>(base + 8);
                uint2 bf = g_W1Frag[(w * 16 + 8 + kc) * 32 + lane];
                mma16816(e0, e1, e2, e3, a0, a2, bf.x, bf.y);
            }
            {
                int j = w * 8 + tg * 2;
                float2 b1v = __half22float2(*reinterpret_cast<const __half2*>(B1h + j));
                *reinterpret_cast<__half2*>(DP + g * 128 + j) =
                    __floats2half2_rn(c0 + e0 + b1v.x, c1 + e1 + b1v.y);
            }
#pragma unroll
            for (int ti = 0; ti < 4; ++ti) {
                int jj = (w * 4 + ti) * 8 + tg * 2;
                float2 bia = __half22float2(*reinterpret_cast<const __half2*>(BIAh + jj));
                *reinterpret_cast<__half2*>(GS + g * 512 + jj) =
                    __floats2half2_rn(acc[ti][0] + bia.x, acc[ti][1] + bia.y);
            }
        }
        __syncthreads();
        // B: e[p] = sum_j W2[j]*tanh(DP[r][j]+XW[p][j]); write (exp(e), exp(e)*FX[p])
        if (tid < R * T) {
            const int p = tid;
            const int r = (p * 1366) >> 16;  // p / 48 for p < 384
            const __half2* dp2 = reinterpret_cast<const __half2*>(DP + r * 128);
            const __half2* xw2 = reinterpret_cast<const __half2*>(XW + p * XW_S);
            float acc = 0.f;
#pragma unroll 16
            for (int j2 = 0; j2 < 64; ++j2) {
                float2 tf = __half22float2(tanh2_fast(__hadd2(dp2[j2], xw2[j2])));
                float2 wv = __half22float2(reinterpret_cast<const __half2*>(W2h)[j2]);
                acc = fmaf(wv.x, tf.x, fmaf(wv.y, tf.y, acc));
            }
            float ex = __expf(acc);               // |e| <= ~6 -> no max needed
            EB2[p] = make_float2(ex, ex * __half2float(FXh[p]));
        }
        __syncthreads();
        // E: per-warp inline softmax-reduction -> y_tilde, then LSTM update
        {
            const int r = tid >> 6;               // uniform per warp (= w>>1)
            // row reduction: lanes 0..23 each load 2 (exp,px) pairs as float4
            float se = 0.f, sp = 0.f;
            if (lane < 24) {
                float4 v = reinterpret_cast<const float4*>(EB2 + r * T)[lane];
                se = v.x + v.z;
                sp = v.y + v.w;
            }
#pragma unroll
            for (int o = 16; o; o >>= 1) {
                se += __shfl_xor_sync(0xffffffffu, se, o);
                sp += __shfl_xor_sync(0xffffffffu, sp, o);
            }
            float yt = __fdividef(sp, se)
                     + FCW[128] * __half2float(YPh[r * T + t]) + FCW[129];
            // elementwise update: 2 consecutive q per thread
            const int q0 = (tid & 63) * 2;
            const __half2* gsr = reinterpret_cast<const __half2*>(GS + r * 512);
            float2 wi_i = __half22float2(*reinterpret_cast<const __half2*>(WIHh + q0));
            float2 wi_f = __half22float2(*reinterpret_cast<const __half2*>(WIHh + 128 + q0));
            float2 wi_g = __half22float2(*reinterpret_cast<const __half2*>(WIHh + 256 + q0));
            float2 wi_o = __half22float2(*reinterpret_cast<const __half2*>(WIHh + 384 + q0));
            float2 g_i = __half22float2(gsr[q0 >> 1]);
            float2 g_f = __half22float2(gsr[(128 + q0) >> 1]);
            float2 g_g = __half22float2(gsr[(256 + q0) >> 1]);
            float2 g_o = __half22float2(gsr[(384 + q0) >> 1]);
            float gi0 = fmaf(wi_i.x, yt, g_i.x), gi1 = fmaf(wi_i.y, yt, g_i.y);
            float gf0 = fmaf(wi_f.x, yt, g_f.x), gf1 = fmaf(wi_f.y, yt, g_f.y);
            float gg0 = fmaf(wi_g.x, yt, g_g.x), gg1 = fmaf(wi_g.y, yt, g_g.y);
            float go0 = fmaf(wi_o.x, yt, g_o.x), go1 = fmaf(wi_o.y, yt, g_o.y);
            float2 si = sigm2f(gi0, gi1);
            float2 sf = sigm2f(gf0, gf1);
            float2 so = sigm2f(go0, go1);
            float2 tg2 = tanh2f(gg0, gg1);
            float2 cv = *reinterpret_cast<const float2*>(CS + r * 128 + q0);
            float cn0 = sf.x * cv.x + si.x * tg2.x;
            float cn1 = sf.y * cv.y + si.y * tg2.y;
            *reinterpret_cast<float2*>(CS + r * 128 + q0) = make_float2(cn0, cn1);
            float2 tc = tanh2f(cn0, cn1);
            *reinterpret_cast<__half2*>(DH + r * DH_S + q0) =
                __floats2half2_rn(so.x * tc.x, so.y * tc.y);
            *reinterpret_cast<__half2*>(CH + r * DH_S + q0) =
                __floats2half2_rn(cn0, cn1);
        }
        __syncthreads();
    }

    // ---- epilogue: per-row inv-sums for final beta ----
    if (tid < 256) {
        const int wr = tid >> 5, l = tid & 31;
        float se = 0.f;
        if (l < 24) {
            float4 v = reinterpret_cast<const float4*>(EB2 + wr * T)[l];
            se = v.x + v.z;
        }
        se = warp_sum(se);
        if (l == 0) YT[wr] = __fdividef(1.0f, se);
    }
    __syncthreads();
    // ---- final context: CT[r][k] = inv[r] * sum_tt exp[r][tt] * X[r][tt][k] ----
    {
        const int k = tid & 127, g2 = tid >> 7;  // g2 in 0..3
        float a0 = 0.f, a1 = 0.f;
#pragma unroll 4
        for (int tt = 0; tt < T; ++tt) {
            a0 += EB2[g2 * T + tt].x       * __half2float(XS[(g2 * T + tt) * XS_S + k]);
            a1 += EB2[(g2 + 4) * T + tt].x * __half2float(XS[((g2 + 4) * T + tt) * XS_S + k]);
        }
        CT[g2 * 128 + k]       = __float2half(a0 * YT[g2]);
        CT[(g2 + 4) * 128 + k] = __float2half(a1 * YT[g2 + 4]);
    }
    __syncthreads();
    // ---- final: y_pred = fcf . [d, context] + fcf_b;  out += y_pred ----
    if (tid < 256) {
        const int wr = tid >> 5, l = tid & 31;
        float a = 0.f;
#pragma unroll
        for (int q = 0; q < 4; ++q) {
            int k = l + 32 * q;
            a += FCF[k] * __half2float(DH[wr * DH_S + k])
               + FCF[128 + k] * __half2float(CT[wr * 128 + k]);
        }
        a = warp_sum(a);
        if (l == 0) out[b0 + wr] += a + FCF[256];
    }
}

// ---------------- launch ----------------
extern "C" void kernel_launch(void* const* d_in, const int* in_sizes, int n_in,
                              void* d_out, int out_size) {
    const float* X     = (const float*)d_in[0];
    const float* yprev = (const float*)d_in[1];
    const float* yskip = (const float*)d_in[2];
    const float* aW1   = (const float*)d_in[3];
    const float* ab1   = (const float*)d_in[4];
    const float* aW2   = (const float*)d_in[5];
    // d_in[6] = attn_b2 (softmax shift-invariant -> unused)
    const float* lWih  = (const float*)d_in[7];
    const float* lWhh  = (const float*)d_in[8];
    const float* lbih  = (const float*)d_in[9];
    const float* lbhh  = (const float*)d_in[10];
    const float* fcW   = (const float*)d_in[11];
    const float* fcb   = (const float*)d_in[12];
    const float* fcfW  = (const float*)d_in[13];
    const float* fcfb  = (const float*)d_in[14];
    const float* gWih  = (const float*)d_in[15];
    const float* gWhh  = (const float*)d_in[16];
    const float* gbih  = (const float*)d_in[17];
    const float* gbhh  = (const float*)d_in[18];
    const float* l1W   = (const float*)d_in[19];
    const float* l1b   = (const float*)d_in[20];
    const float* l2W   = (const float*)d_in[21];
    const float* l2b   = (const float*)d_in[22];
    float* out = (float*)d_out;

    cudaFuncSetAttribute(decoder_kernel, cudaFuncAttributeMaxDynamicSharedMemorySize, SMEM_BYTES);

    // side branch writes out[b] = s_skip + s_linear
    gru_kernel<<<8192 / 128, 128>>>(yskip, yprev, gWih, gWhh, gbih, gbhh,
                                    l1W, l1b, l2W, l2b, out);
    // weight fragment packing
    prep_kernel<<<64, 256>>>(aW1, lWhh);
    // main decoder adds y_pred into out
    decoder_kernel<<<NCTA, NT, SMEM_BYTES>>>(X, yprev, ab1, aW2,
                                             lWih, lbih, lbhh,
                                             fcW, fcb, fcfW, fcfb, out);
}